// round 12
// baseline (speedup 1.0000x reference)
#include <cuda_runtime.h>
#include <cuda_bf16.h>
#include <stdint.h>

#define NB 4
#define NC 64
#define NN 4096

// bf16 hi/lo split operands in MMA-native layouts.
__device__ __nv_bfloat16 g_Qh[NB*NN*NC];   // (B, N, C)
__device__ __nv_bfloat16 g_Ql[NB*NN*NC];
__device__ __nv_bfloat16 g_Kh[NB*NN*NC];   // (B, N, C)
__device__ __nv_bfloat16 g_Kl[NB*NN*NC];
__device__ __nv_bfloat16 g_Vh[NB*NC*NN];   // (B, C, N)
__device__ __nv_bfloat16 g_Vl[NB*NC*NN];

// ---------------------------------------------------------------------------
// Arch-agnostic tensor-core helpers (sm_80+ PTX only: ldmatrix / mma / cp.async)
// ---------------------------------------------------------------------------
__device__ __forceinline__ uint32_t smem_u32(const void* p) {
    uint32_t a;
    asm("{ .reg .u64 t; cvta.to.shared.u64 t, %1; cvt.u32.u64 %0, t; }" : "=r"(a) : "l"(p));
    return a;
}

#define SWZ128(x) ((uint32_t)(x) ^ ((((uint32_t)(x)) >> 3) & 0x70u))
#define SWZ256(x) ((uint32_t)(x) ^ ((((uint32_t)(x)) >> 4) & 0x70u))

__device__ __forceinline__ void ldsm4(uint32_t &r0, uint32_t &r1, uint32_t &r2, uint32_t &r3,
                                      uint32_t a) {
    asm volatile("ldmatrix.sync.aligned.m8n8.x4.shared.b16 {%0,%1,%2,%3}, [%4];"
                 : "=r"(r0), "=r"(r1), "=r"(r2), "=r"(r3) : "r"(a));
}

__device__ __forceinline__ void mma16816(float c[4],
                                         uint32_t a0, uint32_t a1, uint32_t a2, uint32_t a3,
                                         uint32_t b0, uint32_t b1) {
    asm volatile("mma.sync.aligned.m16n8k16.row.col.f32.bf16.bf16.f32 "
                 "{%0,%1,%2,%3}, {%4,%5,%6,%7}, {%8,%9}, {%0,%1,%2,%3};"
                 : "+f"(c[0]), "+f"(c[1]), "+f"(c[2]), "+f"(c[3])
                 : "r"(a0), "r"(a1), "r"(a2), "r"(a3), "r"(b0), "r"(b1));
}

__device__ __forceinline__ void cpasync16(uint32_t s, const void* g) {
    asm volatile("cp.async.cg.shared.global [%0], [%1], 16;"
                 :: "r"(s), "l"(__cvta_generic_to_global(g)) : "memory");
}
#define CP_COMMIT() asm volatile("cp.async.commit_group;" ::: "memory")
#define CP_WAIT1()  asm volatile("cp.async.wait_group 1;" ::: "memory")
#define CP_WAIT0()  asm volatile("cp.async.wait_group 0;" ::: "memory")

// ---------------------------------------------------------------------------
// QKV projection with bf16 hi/lo splitting.
// ---------------------------------------------------------------------------
__global__ __launch_bounds__(256) void qkv_kernel(
    const float* __restrict__ x,
    const float* __restrict__ Wq, const float* __restrict__ bq,
    const float* __restrict__ Wk, const float* __restrict__ bk,
    const float* __restrict__ Wv, const float* __restrict__ bv)
{
    __shared__ float xs[64 * 64];
    __shared__ float wts[64 * 65];

    const int tid = threadIdx.x;
    const int b = blockIdx.y;
    const int n0 = blockIdx.x * 64;

    for (int idx = tid; idx < 4096; idx += 256) {
        int c = idx >> 6, nn = idx & 63;
        xs[idx] = x[(size_t)(b * 64 + c) * 4096 + n0 + nn];
    }

    const int co = tid & 63;
    const int g  = tid >> 6;
    const float* Ws[3] = {Wq, Wk, Wv};
    const float* bs[3] = {bq, bk, bv};

    for (int m = 0; m < 3; m++) {
        __syncthreads();
        for (int idx = tid; idx < 4096; idx += 256)
            wts[(idx & 63) * 65 + (idx >> 6)] = Ws[m][idx];
        __syncthreads();

        float acc[16];
        const float bias = bs[m][co];
        #pragma unroll
        for (int i = 0; i < 16; i++) acc[i] = bias;

        #pragma unroll 4
        for (int c = 0; c < 64; c++) {
            float w = wts[c * 65 + co];
            const float4* xp = (const float4*)(xs + c * 64 + g * 16);
            #pragma unroll
            for (int r = 0; r < 4; r++) {
                float4 xv = xp[r];
                acc[4 * r + 0] += w * xv.x;
                acc[4 * r + 1] += w * xv.y;
                acc[4 * r + 2] += w * xv.z;
                acc[4 * r + 3] += w * xv.w;
            }
        }

        const int nbase = n0 + g * 16;
        if (m < 2) {
            __nv_bfloat16* Dh = (m == 0) ? g_Qh : g_Kh;
            __nv_bfloat16* Dl = (m == 0) ? g_Ql : g_Kl;
            #pragma unroll
            for (int i = 0; i < 16; i++) {
                float a = acc[i];
                __nv_bfloat16 h = __float2bfloat16(a);
                __nv_bfloat16 l = __float2bfloat16(a - __bfloat162float(h));
                size_t off = ((size_t)(b * 4096 + nbase + i)) * 64 + co;
                Dh[off] = h; Dl[off] = l;
            }
        } else {
            unsigned wh[8], wl[8];
            #pragma unroll
            for (int i = 0; i < 8; i++) {
                float a0 = acc[2 * i], a1 = acc[2 * i + 1];
                __nv_bfloat16 h0 = __float2bfloat16(a0);
                __nv_bfloat16 h1 = __float2bfloat16(a1);
                __nv_bfloat16 l0 = __float2bfloat16(a0 - __bfloat162float(h0));
                __nv_bfloat16 l1 = __float2bfloat16(a1 - __bfloat162float(h1));
                wh[i] = (unsigned)__bfloat16_as_ushort(h0) | ((unsigned)__bfloat16_as_ushort(h1) << 16);
                wl[i] = (unsigned)__bfloat16_as_ushort(l0) | ((unsigned)__bfloat16_as_ushort(l1) << 16);
            }
            size_t off = ((size_t)(b * 64 + co)) * 4096 + nbase;
            *(uint4*)(g_Vh + off)     = make_uint4(wh[0], wh[1], wh[2], wh[3]);
            *(uint4*)(g_Vh + off + 8) = make_uint4(wh[4], wh[5], wh[6], wh[7]);
            *(uint4*)(g_Vl + off)     = make_uint4(wl[0], wl[1], wl[2], wl[3]);
            *(uint4*)(g_Vl + off + 8) = make_uint4(wl[4], wl[5], wl[6], wl[7]);
        }
    }
}

// ---------------------------------------------------------------------------
// Fused flash attention (mma.sync m16n8k16 bf16, 3-split S, 3-term PV),
// k-split warp specialization: 512 thr = 16 warps = 2 groups of 8.
// Group g (warps 8g..8g+7) processes chunks [4g, 4g+4) of each 128-key tile.
// Warp wg (=w&7) owns q rows [16wg,16wg+16). Both groups share K/V smem tiles
// -> occupancy doubles (4 warps/SMSP) with no extra smem. Partial O/lsum
// merged in the epilogue via smem.
// smem: K [2][hi/lo][128x64 SW128] 64KB + V [2][hi/lo][64x128 SW256] 64KB.
// ---------------------------------------------------------------------------
#define OFF_K 0u
#define OFF_V 65536u
#define ATTN_SMEM 131072u

__global__ void __launch_bounds__(512, 1) attn_kernel(float* __restrict__ out)
{
    extern __shared__ __align__(1024) char smem[];
    const uint32_t sb = smem_u32(smem);
    const int tid  = threadIdx.x;
    const int lane = tid & 31;
    const int w    = tid >> 5;
    const int wg   = w & 7;        // q-row warp id within group
    const int grp  = w >> 3;       // k-split group 0/1
    const int b    = blockIdx.y;
    const int n0   = blockIdx.x * 128;

    const __nv_bfloat16* Qhg = g_Qh + ((size_t)(b * 4096 + n0)) * 64;
    const __nv_bfloat16* Qlg = g_Ql + ((size_t)(b * 4096 + n0)) * 64;
    const __nv_bfloat16* Khg = g_Kh + ((size_t)b * 4096) * 64;
    const __nv_bfloat16* Klg = g_Kl + ((size_t)b * 4096) * 64;
    const __nv_bfloat16* Vhg = g_Vh + (size_t)b * 64 * 4096;
    const __nv_bfloat16* Vlg = g_Vl + (size_t)b * 64 * 4096;

    // ---- stage Q (hi at OFF_K, lo at +16KB), extract A-fragments ----
    for (int idx = tid; idx < 1024; idx += 512) {
        int row = idx >> 3, u = idx & 7;
        uint32_t d = SWZ128(row * 128 + u * 16);
        *(uint4*)(smem + OFF_K + d)         = *(const uint4*)(Qhg + row * 64 + u * 8);
        *(uint4*)(smem + OFF_K + d + 16384) = *(const uint4*)(Qlg + row * 64 + u * 8);
    }
    __syncthreads();

    uint32_t qh[4][4], ql[4][4];
    {
        int r = wg * 16 + (lane & 15);
        #pragma unroll
        for (int ks = 0; ks < 4; ks++) {
            uint32_t a = sb + OFF_K + SWZ128(r * 128 + ks * 32 + (lane >> 4) * 16);
            ldsm4(qh[ks][0], qh[ks][1], qh[ks][2], qh[ks][3], a);
            ldsm4(ql[ks][0], ql[ks][1], ql[ks][2], ql[ks][3], a + 16384);
        }
    }
    __syncthreads();

    // ---- async tile loader (512 threads) ----
    auto loadKV = [&](int it, int buf) {
        uint32_t kb = sb + OFF_K + (uint32_t)buf * 32768u;
        uint32_t vb = sb + OFF_V + (uint32_t)buf * 32768u;
        const __nv_bfloat16* kh = Khg + (size_t)it * 128 * 64;
        const __nv_bfloat16* kl = Klg + (size_t)it * 128 * 64;
        for (int idx = tid; idx < 1024; idx += 512) {
            int row = idx >> 3, u = idx & 7;
            uint32_t d = kb + SWZ128(row * 128 + u * 16);
            cpasync16(d,         kh + row * 64 + u * 8);
            cpasync16(d + 16384, kl + row * 64 + u * 8);
        }
        for (int idx = tid; idx < 1024; idx += 512) {
            int c = idx >> 4, u = idx & 15;
            uint32_t d = vb + SWZ256(c * 256 + u * 16);
            cpasync16(d,         Vhg + (size_t)c * 4096 + it * 128 + u * 8);
            cpasync16(d + 16384, Vlg + (size_t)c * 4096 + it * 128 + u * 8);
        }
        CP_COMMIT();
    };

    loadKV(0, 0);
    loadKV(1, 1);

    float oacc[8][4];
    #pragma unroll
    for (int i = 0; i < 8; i++)
        #pragma unroll
        for (int j = 0; j < 4; j++) oacc[i][j] = 0.0f;
    float lsum0 = 0.0f, lsum1 = 0.0f;

    for (int it = 0; it < 32; it++) {
        if (it + 1 < 32) { CP_WAIT1(); } else { CP_WAIT0(); }
        __syncthreads();

        const uint32_t kb = sb + OFF_K + (uint32_t)(it & 1) * 32768u;
        const uint32_t vb = sb + OFF_V + (uint32_t)(it & 1) * 32768u;

        // ---- S for chunk kc (two 8-key sub-tiles) -> raw scores sv[2][4] ----
        auto S_step = [&](int kc, float sv[2][4]) {
            #pragma unroll
            for (int j = 0; j < 2; j++) {
                const int nt = kc * 2 + j;
                uint32_t bh[8], bl[8];
                const int br = nt * 8 + (lane & 7);
                #pragma unroll
                for (int ks2 = 0; ks2 < 2; ks2++) {
                    uint32_t a = kb + SWZ128(br * 128 + ks2 * 64 + (lane >> 3) * 16);
                    ldsm4(bh[4*ks2+0], bh[4*ks2+1], bh[4*ks2+2], bh[4*ks2+3], a);
                    ldsm4(bl[4*ks2+0], bl[4*ks2+1], bl[4*ks2+2], bl[4*ks2+3], a + 16384);
                }
                float sa[4] = {0.f, 0.f, 0.f, 0.f};
                float sb2[4] = {0.f, 0.f, 0.f, 0.f};
                float sc[4] = {0.f, 0.f, 0.f, 0.f};
                #pragma unroll
                for (int ks = 0; ks < 4; ks++) {
                    mma16816(sa,  qh[ks][0], qh[ks][1], qh[ks][2], qh[ks][3], bh[2*ks], bh[2*ks+1]);
                    mma16816(sb2, qh[ks][0], qh[ks][1], qh[ks][2], qh[ks][3], bl[2*ks], bl[2*ks+1]);
                    mma16816(sc,  ql[ks][0], ql[ks][1], ql[ks][2], ql[ks][3], bh[2*ks], bh[2*ks+1]);
                }
                #pragma unroll
                for (int i = 0; i < 4; i++) sv[j][i] = (sa[i] + sb2[i]) + sc[i];
            }
        };

        // ---- PV for chunk cp using held P fragments ----
        auto PV_step = [&](int cp, const uint32_t pa_h[4], const uint32_t pa_l[4]) {
            #pragma unroll
            for (int cnp = 0; cnp < 4; cnp++) {
                const int row = cnp * 16 + (lane >> 4) * 8 + (lane & 7);
                const int chunk = cp * 2 + ((lane >> 3) & 1);
                uint32_t a = vb + SWZ256(row * 256 + chunk * 16);
                uint32_t vh[4], vl[4];
                ldsm4(vh[0], vh[1], vh[2], vh[3], a);
                ldsm4(vl[0], vl[1], vl[2], vl[3], a + 16384);

                mma16816(oacc[2*cnp],   pa_h[0], pa_h[1], pa_h[2], pa_h[3], vh[0], vh[1]);
                mma16816(oacc[2*cnp],   pa_h[0], pa_h[1], pa_h[2], pa_h[3], vl[0], vl[1]);
                mma16816(oacc[2*cnp],   pa_l[0], pa_l[1], pa_l[2], pa_l[3], vh[0], vh[1]);
                mma16816(oacc[2*cnp+1], pa_h[0], pa_h[1], pa_h[2], pa_h[3], vh[2], vh[3]);
                mma16816(oacc[2*cnp+1], pa_h[0], pa_h[1], pa_h[2], pa_h[3], vl[2], vl[3]);
                mma16816(oacc[2*cnp+1], pa_l[0], pa_l[1], pa_l[2], pa_l[3], vh[2], vh[3]);
            }
        };

        // ---- softmax on raw scores -> P fragments ----
        auto softmax_step = [&](const float sv[2][4], uint32_t pa_h[4], uint32_t pa_l[4]) {
            #pragma unroll
            for (int j = 0; j < 2; j++) {
                float p0 = __expf(sv[j][0] - 40.0f);
                float p1 = __expf(sv[j][1] - 40.0f);
                float p2 = __expf(sv[j][2] - 40.0f);
                float p3 = __expf(sv[j][3] - 40.0f);
                lsum0 += p0 + p1;
                lsum1 += p2 + p3;

                __nv_bfloat162 h01 = __float22bfloat162_rn(make_float2(p0, p1));
                __nv_bfloat162 h23 = __float22bfloat162_rn(make_float2(p2, p3));
                float2 f01 = __bfloat1622float2(h01);
                float2 f23 = __bfloat1622float2(h23);
                __nv_bfloat162 l01 = __float22bfloat162_rn(make_float2(p0 - f01.x, p1 - f01.y));
                __nv_bfloat162 l23 = __float22bfloat162_rn(make_float2(p2 - f23.x, p3 - f23.y));

                pa_h[2*j]   = *(uint32_t*)&h01;
                pa_h[2*j+1] = *(uint32_t*)&h23;
                pa_l[2*j]   = *(uint32_t*)&l01;
                pa_l[2*j+1] = *(uint32_t*)&l23;
            }
        };

        // ---- this group's 4 chunks, pipelined: peel first chunk ----
        const int kc0 = grp * 4;
        uint32_t pa_h[4], pa_l[4];
        {
            float sv[2][4];
            S_step(kc0, sv);
            softmax_step(sv, pa_h, pa_l);
        }
        #pragma unroll 1
        for (int kc = kc0 + 1; kc < kc0 + 4; kc++) {
            float sv[2][4];
            S_step(kc, sv);               // S MMAs for this chunk
            PV_step(kc - 1, pa_h, pa_l);  // independent PV burst hides S latency
            softmax_step(sv, pa_h, pa_l); // new P frags for next iteration
        }
        PV_step(kc0 + 3, pa_h, pa_l);

        __syncthreads();
        if (it + 2 < 32) loadKV(it + 2, it & 1);
    }

    // ---- epilogue: merge group partials, normalize, store (B,C,N) ----
    lsum0 += __shfl_xor_sync(0xffffffffu, lsum0, 1);
    lsum0 += __shfl_xor_sync(0xffffffffu, lsum0, 2);
    lsum1 += __shfl_xor_sync(0xffffffffu, lsum1, 1);
    lsum1 += __shfl_xor_sync(0xffffffffu, lsum1, 2);

    // pO in retired K buf0 region (32KB, pitch 128); pL in retired V buf0.
    float* pO = (float*)smem;                  // [64c][128q]
    float* pL = (float*)(smem + 65536);        // [128]
    const int q0 = wg * 16 + (lane >> 2);

    if (grp == 1) {
        #pragma unroll
        for (int cn = 0; cn < 8; cn++) {
            const int c = cn * 8 + 2 * (lane & 3);
            pO[c * 128 + q0]           = oacc[cn][0];
            pO[(c + 1) * 128 + q0]     = oacc[cn][1];
            pO[c * 128 + q0 + 8]       = oacc[cn][2];
            pO[(c + 1) * 128 + q0 + 8] = oacc[cn][3];
        }
        if ((lane & 3) == 0) { pL[q0] = lsum0; pL[q0 + 8] = lsum1; }
    }
    __syncthreads();
    if (grp == 0) {
        const float inv0 = 1.0f / (lsum0 + pL[q0]);
        const float inv1 = 1.0f / (lsum1 + pL[q0 + 8]);
        #pragma unroll
        for (int cn = 0; cn < 8; cn++) {
            const int c = cn * 8 + 2 * (lane & 3);
            pO[c * 128 + q0]           = (oacc[cn][0] + pO[c * 128 + q0]) * inv0;
            pO[(c + 1) * 128 + q0]     = (oacc[cn][1] + pO[(c + 1) * 128 + q0]) * inv0;
            pO[c * 128 + q0 + 8]       = (oacc[cn][2] + pO[c * 128 + q0 + 8]) * inv1;
            pO[(c + 1) * 128 + q0 + 8] = (oacc[cn][3] + pO[(c + 1) * 128 + q0 + 8]) * inv1;
        }
    }
    __syncthreads();

    float* outb = out + (size_t)b * 64 * 4096;
    for (int idx = tid; idx < 8192; idx += 512) {
        int c = idx >> 7, qq = idx & 127;
        outb[(size_t)c * 4096 + n0 + qq] = pO[idx];
    }
}

extern "C" void kernel_launch(void* const* d_in, const int* in_sizes, int n_in,
                              void* d_out, int out_size)
{
    const float* x  = (const float*)d_in[0];
    const float* Wq = (const float*)d_in[1];
    const float* bq = (const float*)d_in[2];
    const float* Wk = (const float*)d_in[3];
    const float* bk = (const float*)d_in[4];
    const float* Wv = (const float*)d_in[5];
    const float* bv = (const float*)d_in[6];
    float* out = (float*)d_out;

    qkv_kernel<<<dim3(64, NB), 256>>>(x, Wq, bq, Wk, bk, Wv, bv);

    cudaFuncSetAttribute(attn_kernel, cudaFuncAttributeMaxDynamicSharedMemorySize, ATTN_SMEM);
    attn_kernel<<<dim3(32, NB), 512, ATTN_SMEM>>>(out);
}

// round 13
// speedup vs baseline: 1.0228x; 1.0228x over previous
#include <cuda_runtime.h>
#include <cuda_bf16.h>
#include <stdint.h>

#define NB 4
#define NC 64
#define NN 4096

// bf16 hi/lo split operands in MMA-native layouts.
__device__ __nv_bfloat16 g_Qh[NB*NN*NC];   // (B, N, C)
__device__ __nv_bfloat16 g_Ql[NB*NN*NC];
__device__ __nv_bfloat16 g_Kh[NB*NN*NC];   // (B, N, C)
__device__ __nv_bfloat16 g_Kl[NB*NN*NC];
__device__ __nv_bfloat16 g_Vh[NB*NC*NN];   // (B, C, N)
__device__ __nv_bfloat16 g_Vl[NB*NC*NN];

// ---------------------------------------------------------------------------
// Arch-agnostic tensor-core helpers (sm_80+ PTX only: ldmatrix / mma / cp.async)
// ---------------------------------------------------------------------------
__device__ __forceinline__ uint32_t smem_u32(const void* p) {
    uint32_t a;
    asm("{ .reg .u64 t; cvta.to.shared.u64 t, %1; cvt.u32.u64 %0, t; }" : "=r"(a) : "l"(p));
    return a;
}

#define SWZ128(x) ((uint32_t)(x) ^ ((((uint32_t)(x)) >> 3) & 0x70u))
#define SWZ256(x) ((uint32_t)(x) ^ ((((uint32_t)(x)) >> 4) & 0x70u))

__device__ __forceinline__ void ldsm4(uint32_t &r0, uint32_t &r1, uint32_t &r2, uint32_t &r3,
                                      uint32_t a) {
    asm volatile("ldmatrix.sync.aligned.m8n8.x4.shared.b16 {%0,%1,%2,%3}, [%4];"
                 : "=r"(r0), "=r"(r1), "=r"(r2), "=r"(r3) : "r"(a));
}

__device__ __forceinline__ void mma16816(float c[4],
                                         uint32_t a0, uint32_t a1, uint32_t a2, uint32_t a3,
                                         uint32_t b0, uint32_t b1) {
    asm volatile("mma.sync.aligned.m16n8k16.row.col.f32.bf16.bf16.f32 "
                 "{%0,%1,%2,%3}, {%4,%5,%6,%7}, {%8,%9}, {%0,%1,%2,%3};"
                 : "+f"(c[0]), "+f"(c[1]), "+f"(c[2]), "+f"(c[3])
                 : "r"(a0), "r"(a1), "r"(a2), "r"(a3), "r"(b0), "r"(b1));
}

__device__ __forceinline__ void cpasync16(uint32_t s, const void* g) {
    asm volatile("cp.async.cg.shared.global [%0], [%1], 16;"
                 :: "r"(s), "l"(__cvta_generic_to_global(g)) : "memory");
}
#define CP_COMMIT() asm volatile("cp.async.commit_group;" ::: "memory")
#define CP_WAIT1()  asm volatile("cp.async.wait_group 1;" ::: "memory")
#define CP_WAIT0()  asm volatile("cp.async.wait_group 0;" ::: "memory")

// ---------------------------------------------------------------------------
// QKV projection with bf16 hi/lo splitting; one matrix per blockIdx.z.
// ---------------------------------------------------------------------------
__global__ __launch_bounds__(256) void qkv_kernel(
    const float* __restrict__ x,
    const float* __restrict__ Wq, const float* __restrict__ bq,
    const float* __restrict__ Wk, const float* __restrict__ bk,
    const float* __restrict__ Wv, const float* __restrict__ bv)
{
    __shared__ float xs[64 * 64];
    __shared__ float wts[64 * 65];

    const int tid = threadIdx.x;
    const int b = blockIdx.y;
    const int n0 = blockIdx.x * 64;
    const int m  = blockIdx.z;

    const float* W = (m == 0) ? Wq : (m == 1) ? Wk : Wv;
    const float* bias_v = (m == 0) ? bq : (m == 1) ? bk : bv;

    for (int idx = tid; idx < 4096; idx += 256) {
        int c = idx >> 6, nn = idx & 63;
        xs[idx] = x[(size_t)(b * 64 + c) * 4096 + n0 + nn];
    }
    for (int idx = tid; idx < 4096; idx += 256)
        wts[(idx & 63) * 65 + (idx >> 6)] = W[idx];
    __syncthreads();

    const int co = tid & 63;
    const int g  = tid >> 6;

    float acc[16];
    const float bias = bias_v[co];
    #pragma unroll
    for (int i = 0; i < 16; i++) acc[i] = bias;

    #pragma unroll 4
    for (int c = 0; c < 64; c++) {
        float w = wts[c * 65 + co];
        const float4* xp = (const float4*)(xs + c * 64 + g * 16);
        #pragma unroll
        for (int r = 0; r < 4; r++) {
            float4 xv = xp[r];
            acc[4 * r + 0] += w * xv.x;
            acc[4 * r + 1] += w * xv.y;
            acc[4 * r + 2] += w * xv.z;
            acc[4 * r + 3] += w * xv.w;
        }
    }

    const int nbase = n0 + g * 16;
    if (m < 2) {
        __nv_bfloat16* Dh = (m == 0) ? g_Qh : g_Kh;
        __nv_bfloat16* Dl = (m == 0) ? g_Ql : g_Kl;
        #pragma unroll
        for (int i = 0; i < 16; i++) {
            float a = acc[i];
            __nv_bfloat16 h = __float2bfloat16(a);
            __nv_bfloat16 l = __float2bfloat16(a - __bfloat162float(h));
            size_t off = ((size_t)(b * 4096 + nbase + i)) * 64 + co;
            Dh[off] = h; Dl[off] = l;
        }
    } else {
        unsigned wh[8], wl[8];
        #pragma unroll
        for (int i = 0; i < 8; i++) {
            float a0 = acc[2 * i], a1 = acc[2 * i + 1];
            __nv_bfloat16 h0 = __float2bfloat16(a0);
            __nv_bfloat16 h1 = __float2bfloat16(a1);
            __nv_bfloat16 l0 = __float2bfloat16(a0 - __bfloat162float(h0));
            __nv_bfloat16 l1 = __float2bfloat16(a1 - __bfloat162float(h1));
            wh[i] = (unsigned)__bfloat16_as_ushort(h0) | ((unsigned)__bfloat16_as_ushort(h1) << 16);
            wl[i] = (unsigned)__bfloat16_as_ushort(l0) | ((unsigned)__bfloat16_as_ushort(l1) << 16);
        }
        size_t off = ((size_t)(b * 64 + co)) * 4096 + nbase;
        *(uint4*)(g_Vh + off)     = make_uint4(wh[0], wh[1], wh[2], wh[3]);
        *(uint4*)(g_Vh + off + 8) = make_uint4(wh[4], wh[5], wh[6], wh[7]);
        *(uint4*)(g_Vl + off)     = make_uint4(wl[0], wl[1], wl[2], wl[3]);
        *(uint4*)(g_Vl + off + 8) = make_uint4(wl[4], wl[5], wl[6], wl[7]);
    }
}

// ---------------------------------------------------------------------------
// Fused flash attention (mma.sync m16n8k16 bf16, 3-split S, 3-term PV).
// 256 thr = 8 warps = 4 q-warps x 2 k-groups. Each warp owns 32 q rows
// (2 m16 subtiles) -> every B-fragment (K/V) load feeds 2x MMAs: smem
// crossbar traffic halves vs 16-row warps. Group g does chunks [4g,4g+4).
// smem: K [2][hi/lo][128x64 SW128] 64KB + V [2][hi/lo][64x128 SW256] 64KB.
// ---------------------------------------------------------------------------
#define OFF_K 0u
#define OFF_V 65536u
#define ATTN_SMEM 131072u

__global__ void __launch_bounds__(256, 1) attn_kernel(float* __restrict__ out)
{
    extern __shared__ __align__(1024) char smem[];
    const uint32_t sb = smem_u32(smem);
    const int tid  = threadIdx.x;
    const int lane = tid & 31;
    const int w    = tid >> 5;
    const int wq   = w & 3;        // q warp: rows [32wq, 32wq+32)
    const int grp  = w >> 2;       // k-split group 0/1
    const int b    = blockIdx.y;
    const int n0   = blockIdx.x * 128;

    const __nv_bfloat16* Qhg = g_Qh + ((size_t)(b * 4096 + n0)) * 64;
    const __nv_bfloat16* Qlg = g_Ql + ((size_t)(b * 4096 + n0)) * 64;
    const __nv_bfloat16* Khg = g_Kh + ((size_t)b * 4096) * 64;
    const __nv_bfloat16* Klg = g_Kl + ((size_t)b * 4096) * 64;
    const __nv_bfloat16* Vhg = g_Vh + (size_t)b * 64 * 4096;
    const __nv_bfloat16* Vlg = g_Vl + (size_t)b * 64 * 4096;

    // ---- stage Q (hi at OFF_K, lo at +16KB), extract A-fragments ----
    for (int idx = tid; idx < 1024; idx += 256) {
        int row = idx >> 3, u = idx & 7;
        uint32_t d = SWZ128(row * 128 + u * 16);
        *(uint4*)(smem + OFF_K + d)         = *(const uint4*)(Qhg + row * 64 + u * 8);
        *(uint4*)(smem + OFF_K + d + 16384) = *(const uint4*)(Qlg + row * 64 + u * 8);
    }
    __syncthreads();

    uint32_t qh[2][4][4], ql[2][4][4];
    #pragma unroll
    for (int mi = 0; mi < 2; mi++) {
        int r = wq * 32 + mi * 16 + (lane & 15);
        #pragma unroll
        for (int ks = 0; ks < 4; ks++) {
            uint32_t a = sb + OFF_K + SWZ128(r * 128 + ks * 32 + (lane >> 4) * 16);
            ldsm4(qh[mi][ks][0], qh[mi][ks][1], qh[mi][ks][2], qh[mi][ks][3], a);
            ldsm4(ql[mi][ks][0], ql[mi][ks][1], ql[mi][ks][2], ql[mi][ks][3], a + 16384);
        }
    }
    __syncthreads();

    // ---- async tile loader ----
    auto loadKV = [&](int it, int buf) {
        uint32_t kb = sb + OFF_K + (uint32_t)buf * 32768u;
        uint32_t vb = sb + OFF_V + (uint32_t)buf * 32768u;
        const __nv_bfloat16* kh = Khg + (size_t)it * 128 * 64;
        const __nv_bfloat16* kl = Klg + (size_t)it * 128 * 64;
        for (int idx = tid; idx < 1024; idx += 256) {
            int row = idx >> 3, u = idx & 7;
            uint32_t d = kb + SWZ128(row * 128 + u * 16);
            cpasync16(d,         kh + row * 64 + u * 8);
            cpasync16(d + 16384, kl + row * 64 + u * 8);
        }
        for (int idx = tid; idx < 1024; idx += 256) {
            int c = idx >> 4, u = idx & 15;
            uint32_t d = vb + SWZ256(c * 256 + u * 16);
            cpasync16(d,         Vhg + (size_t)c * 4096 + it * 128 + u * 8);
            cpasync16(d + 16384, Vlg + (size_t)c * 4096 + it * 128 + u * 8);
        }
        CP_COMMIT();
    };

    loadKV(0, 0);
    loadKV(1, 1);

    float oacc[2][8][4];
    #pragma unroll
    for (int mi = 0; mi < 2; mi++)
        #pragma unroll
        for (int i = 0; i < 8; i++)
            #pragma unroll
            for (int j = 0; j < 4; j++) oacc[mi][i][j] = 0.0f;
    float lsum[2][2] = {{0.f, 0.f}, {0.f, 0.f}};

    for (int it = 0; it < 32; it++) {
        if (it + 1 < 32) { CP_WAIT1(); } else { CP_WAIT0(); }
        __syncthreads();

        const uint32_t kb = sb + OFF_K + (uint32_t)(it & 1) * 32768u;
        const uint32_t vb = sb + OFF_V + (uint32_t)(it & 1) * 32768u;

        // ---- S for chunk kc: B-frags shared across both m-subtiles ----
        auto S_step = [&](int kc, float sv[2][2][4]) {
            #pragma unroll
            for (int j = 0; j < 2; j++) {
                const int nt = kc * 2 + j;
                uint32_t bh[8], bl[8];
                const int br = nt * 8 + (lane & 7);
                #pragma unroll
                for (int ks2 = 0; ks2 < 2; ks2++) {
                    uint32_t a = kb + SWZ128(br * 128 + ks2 * 64 + (lane >> 3) * 16);
                    ldsm4(bh[4*ks2+0], bh[4*ks2+1], bh[4*ks2+2], bh[4*ks2+3], a);
                    ldsm4(bl[4*ks2+0], bl[4*ks2+1], bl[4*ks2+2], bl[4*ks2+3], a + 16384);
                }
                #pragma unroll
                for (int mi = 0; mi < 2; mi++) {
                    float sa[4] = {0.f, 0.f, 0.f, 0.f};
                    float sb2[4] = {0.f, 0.f, 0.f, 0.f};
                    float sc[4] = {0.f, 0.f, 0.f, 0.f};
                    #pragma unroll
                    for (int ks = 0; ks < 4; ks++) {
                        mma16816(sa,  qh[mi][ks][0], qh[mi][ks][1], qh[mi][ks][2], qh[mi][ks][3], bh[2*ks], bh[2*ks+1]);
                        mma16816(sb2, qh[mi][ks][0], qh[mi][ks][1], qh[mi][ks][2], qh[mi][ks][3], bl[2*ks], bl[2*ks+1]);
                        mma16816(sc,  ql[mi][ks][0], ql[mi][ks][1], ql[mi][ks][2], ql[mi][ks][3], bh[2*ks], bh[2*ks+1]);
                    }
                    #pragma unroll
                    for (int i = 0; i < 4; i++) sv[mi][j][i] = (sa[i] + sb2[i]) + sc[i];
                }
            }
        };

        // ---- PV for chunk cp: V-frags shared across both m-subtiles ----
        auto PV_step = [&](int cp, const uint32_t pa_h[2][4], const uint32_t pa_l[2][4]) {
            #pragma unroll
            for (int cnp = 0; cnp < 4; cnp++) {
                const int row = cnp * 16 + (lane >> 4) * 8 + (lane & 7);
                const int chunk = cp * 2 + ((lane >> 3) & 1);
                uint32_t a = vb + SWZ256(row * 256 + chunk * 16);
                uint32_t vh[4], vl[4];
                ldsm4(vh[0], vh[1], vh[2], vh[3], a);
                ldsm4(vl[0], vl[1], vl[2], vl[3], a + 16384);

                #pragma unroll
                for (int mi = 0; mi < 2; mi++) {
                    mma16816(oacc[mi][2*cnp],   pa_h[mi][0], pa_h[mi][1], pa_h[mi][2], pa_h[mi][3], vh[0], vh[1]);
                    mma16816(oacc[mi][2*cnp],   pa_h[mi][0], pa_h[mi][1], pa_h[mi][2], pa_h[mi][3], vl[0], vl[1]);
                    mma16816(oacc[mi][2*cnp],   pa_l[mi][0], pa_l[mi][1], pa_l[mi][2], pa_l[mi][3], vh[0], vh[1]);
                    mma16816(oacc[mi][2*cnp+1], pa_h[mi][0], pa_h[mi][1], pa_h[mi][2], pa_h[mi][3], vh[2], vh[3]);
                    mma16816(oacc[mi][2*cnp+1], pa_h[mi][0], pa_h[mi][1], pa_h[mi][2], pa_h[mi][3], vl[2], vl[3]);
                    mma16816(oacc[mi][2*cnp+1], pa_l[mi][0], pa_l[mi][1], pa_l[mi][2], pa_l[mi][3], vh[2], vh[3]);
                }
            }
        };

        // ---- softmax -> P fragments (per m-subtile) ----
        auto softmax_step = [&](const float sv[2][2][4], uint32_t pa_h[2][4], uint32_t pa_l[2][4]) {
            #pragma unroll
            for (int mi = 0; mi < 2; mi++) {
                #pragma unroll
                for (int j = 0; j < 2; j++) {
                    float p0 = __expf(sv[mi][j][0] - 40.0f);
                    float p1 = __expf(sv[mi][j][1] - 40.0f);
                    float p2 = __expf(sv[mi][j][2] - 40.0f);
                    float p3 = __expf(sv[mi][j][3] - 40.0f);
                    lsum[mi][0] += p0 + p1;
                    lsum[mi][1] += p2 + p3;

                    __nv_bfloat162 h01 = __float22bfloat162_rn(make_float2(p0, p1));
                    __nv_bfloat162 h23 = __float22bfloat162_rn(make_float2(p2, p3));
                    float2 f01 = __bfloat1622float2(h01);
                    float2 f23 = __bfloat1622float2(h23);
                    __nv_bfloat162 l01 = __float22bfloat162_rn(make_float2(p0 - f01.x, p1 - f01.y));
                    __nv_bfloat162 l23 = __float22bfloat162_rn(make_float2(p2 - f23.x, p3 - f23.y));

                    pa_h[mi][2*j]   = *(uint32_t*)&h01;
                    pa_h[mi][2*j+1] = *(uint32_t*)&h23;
                    pa_l[mi][2*j]   = *(uint32_t*)&l01;
                    pa_l[mi][2*j+1] = *(uint32_t*)&l23;
                }
            }
        };

        // ---- this group's 4 chunks, pipelined: peel first chunk ----
        const int kc0 = grp * 4;
        uint32_t pa_h[2][4], pa_l[2][4];
        {
            float sv[2][2][4];
            S_step(kc0, sv);
            softmax_step(sv, pa_h, pa_l);
        }
        #pragma unroll 1
        for (int kc = kc0 + 1; kc < kc0 + 4; kc++) {
            float sv[2][2][4];
            S_step(kc, sv);
            PV_step(kc - 1, pa_h, pa_l);
            softmax_step(sv, pa_h, pa_l);
        }
        PV_step(kc0 + 3, pa_h, pa_l);

        __syncthreads();
        if (it + 2 < 32) loadKV(it + 2, it & 1);
    }

    // ---- epilogue: merge group partials, normalize, store (B,C,N) ----
    #pragma unroll
    for (int mi = 0; mi < 2; mi++) {
        #pragma unroll
        for (int h2 = 0; h2 < 2; h2++) {
            lsum[mi][h2] += __shfl_xor_sync(0xffffffffu, lsum[mi][h2], 1);
            lsum[mi][h2] += __shfl_xor_sync(0xffffffffu, lsum[mi][h2], 2);
        }
    }

    float* pO = (float*)smem;                  // [64c][128q] 32KB
    float* pL = (float*)(smem + 65536);        // [128]

    if (grp == 1) {
        #pragma unroll
        for (int mi = 0; mi < 2; mi++) {
            const int q0 = wq * 32 + mi * 16 + (lane >> 2);
            #pragma unroll
            for (int cn = 0; cn < 8; cn++) {
                const int c = cn * 8 + 2 * (lane & 3);
                pO[c * 128 + q0]           = oacc[mi][cn][0];
                pO[(c + 1) * 128 + q0]     = oacc[mi][cn][1];
                pO[c * 128 + q0 + 8]       = oacc[mi][cn][2];
                pO[(c + 1) * 128 + q0 + 8] = oacc[mi][cn][3];
            }
            if ((lane & 3) == 0) { pL[q0] = lsum[mi][0]; pL[q0 + 8] = lsum[mi][1]; }
        }
    }
    __syncthreads();
    if (grp == 0) {
        #pragma unroll
        for (int mi = 0; mi < 2; mi++) {
            const int q0 = wq * 32 + mi * 16 + (lane >> 2);
            const float inv0 = 1.0f / (lsum[mi][0] + pL[q0]);
            const float inv1 = 1.0f / (lsum[mi][1] + pL[q0 + 8]);
            #pragma unroll
            for (int cn = 0; cn < 8; cn++) {
                const int c = cn * 8 + 2 * (lane & 3);
                pO[c * 128 + q0]           = (oacc[mi][cn][0] + pO[c * 128 + q0]) * inv0;
                pO[(c + 1) * 128 + q0]     = (oacc[mi][cn][1] + pO[(c + 1) * 128 + q0]) * inv0;
                pO[c * 128 + q0 + 8]       = (oacc[mi][cn][2] + pO[c * 128 + q0 + 8]) * inv1;
                pO[(c + 1) * 128 + q0 + 8] = (oacc[mi][cn][3] + pO[(c + 1) * 128 + q0 + 8]) * inv1;
            }
        }
    }
    __syncthreads();

    float* outb = out + (size_t)b * 64 * 4096;
    for (int idx = tid; idx < 8192; idx += 256) {
        int c = idx >> 7, qq = idx & 127;
        outb[(size_t)c * 4096 + n0 + qq] = pO[idx];
    }
}

extern "C" void kernel_launch(void* const* d_in, const int* in_sizes, int n_in,
                              void* d_out, int out_size)
{
    const float* x  = (const float*)d_in[0];
    const float* Wq = (const float*)d_in[1];
    const float* bq = (const float*)d_in[2];
    const float* Wk = (const float*)d_in[3];
    const float* bk = (const float*)d_in[4];
    const float* Wv = (const float*)d_in[5];
    const float* bv = (const float*)d_in[6];
    float* out = (float*)d_out;

    qkv_kernel<<<dim3(64, NB, 3), 256>>>(x, Wq, bq, Wk, bk, Wv, bv);

    cudaFuncSetAttribute(attn_kernel, cudaFuncAttributeMaxDynamicSharedMemorySize, ATTN_SMEM);
    attn_kernel<<<dim3(32, NB), 256, ATTN_SMEM>>>(out);
}

// round 14
// speedup vs baseline: 1.1110x; 1.0862x over previous
#include <cuda_runtime.h>
#include <cuda_bf16.h>
#include <cuda_fp16.h>
#include <stdint.h>

#define NB 4
#define NC 64
#define NN 4096

// bf16 hi/lo split Q/K + fp16 single V, MMA-native layouts.
__device__ __nv_bfloat16 g_Qh[NB*NN*NC];   // (B, N, C)
__device__ __nv_bfloat16 g_Ql[NB*NN*NC];
__device__ __nv_bfloat16 g_Kh[NB*NN*NC];   // (B, N, C)
__device__ __nv_bfloat16 g_Kl[NB*NN*NC];
__device__ __half        g_Vf[NB*NC*NN];   // (B, C, N)

// ---------------------------------------------------------------------------
// Arch-agnostic tensor-core helpers (sm_80+ PTX only: ldmatrix / mma / cp.async)
// ---------------------------------------------------------------------------
__device__ __forceinline__ uint32_t smem_u32(const void* p) {
    uint32_t a;
    asm("{ .reg .u64 t; cvta.to.shared.u64 t, %1; cvt.u32.u64 %0, t; }" : "=r"(a) : "l"(p));
    return a;
}

#define SWZ128(x) ((uint32_t)(x) ^ ((((uint32_t)(x)) >> 3) & 0x70u))
#define SWZ256(x) ((uint32_t)(x) ^ ((((uint32_t)(x)) >> 4) & 0x70u))

__device__ __forceinline__ void ldsm4(uint32_t &r0, uint32_t &r1, uint32_t &r2, uint32_t &r3,
                                      uint32_t a) {
    asm volatile("ldmatrix.sync.aligned.m8n8.x4.shared.b16 {%0,%1,%2,%3}, [%4];"
                 : "=r"(r0), "=r"(r1), "=r"(r2), "=r"(r3) : "r"(a));
}

__device__ __forceinline__ void mma16816(float c[4],
                                         uint32_t a0, uint32_t a1, uint32_t a2, uint32_t a3,
                                         uint32_t b0, uint32_t b1) {
    asm volatile("mma.sync.aligned.m16n8k16.row.col.f32.bf16.bf16.f32 "
                 "{%0,%1,%2,%3}, {%4,%5,%6,%7}, {%8,%9}, {%0,%1,%2,%3};"
                 : "+f"(c[0]), "+f"(c[1]), "+f"(c[2]), "+f"(c[3])
                 : "r"(a0), "r"(a1), "r"(a2), "r"(a3), "r"(b0), "r"(b1));
}

__device__ __forceinline__ void mma16816h(float c[4],
                                          uint32_t a0, uint32_t a1, uint32_t a2, uint32_t a3,
                                          uint32_t b0, uint32_t b1) {
    asm volatile("mma.sync.aligned.m16n8k16.row.col.f32.f16.f16.f32 "
                 "{%0,%1,%2,%3}, {%4,%5,%6,%7}, {%8,%9}, {%0,%1,%2,%3};"
                 : "+f"(c[0]), "+f"(c[1]), "+f"(c[2]), "+f"(c[3])
                 : "r"(a0), "r"(a1), "r"(a2), "r"(a3), "r"(b0), "r"(b1));
}

__device__ __forceinline__ void cpasync16(uint32_t s, const void* g) {
    asm volatile("cp.async.cg.shared.global [%0], [%1], 16;"
                 :: "r"(s), "l"(__cvta_generic_to_global(g)) : "memory");
}
#define CP_COMMIT() asm volatile("cp.async.commit_group;" ::: "memory")
#define CP_WAIT1()  asm volatile("cp.async.wait_group 1;" ::: "memory")
#define CP_WAIT0()  asm volatile("cp.async.wait_group 0;" ::: "memory")

// ---------------------------------------------------------------------------
// QKV projection: Q/K bf16 hi/lo, V fp16 single; one matrix per blockIdx.z.
// ---------------------------------------------------------------------------
__global__ __launch_bounds__(256) void qkv_kernel(
    const float* __restrict__ x,
    const float* __restrict__ Wq, const float* __restrict__ bq,
    const float* __restrict__ Wk, const float* __restrict__ bk,
    const float* __restrict__ Wv, const float* __restrict__ bv)
{
    __shared__ float xs[64 * 64];
    __shared__ float wts[64 * 65];

    const int tid = threadIdx.x;
    const int b = blockIdx.y;
    const int n0 = blockIdx.x * 64;
    const int m  = blockIdx.z;

    const float* W = (m == 0) ? Wq : (m == 1) ? Wk : Wv;
    const float* bias_v = (m == 0) ? bq : (m == 1) ? bk : bv;

    for (int idx = tid; idx < 4096; idx += 256) {
        int c = idx >> 6, nn = idx & 63;
        xs[idx] = x[(size_t)(b * 64 + c) * 4096 + n0 + nn];
    }
    for (int idx = tid; idx < 4096; idx += 256)
        wts[(idx & 63) * 65 + (idx >> 6)] = W[idx];
    __syncthreads();

    const int co = tid & 63;
    const int g  = tid >> 6;

    float acc[16];
    const float bias = bias_v[co];
    #pragma unroll
    for (int i = 0; i < 16; i++) acc[i] = bias;

    #pragma unroll 4
    for (int c = 0; c < 64; c++) {
        float w = wts[c * 65 + co];
        const float4* xp = (const float4*)(xs + c * 64 + g * 16);
        #pragma unroll
        for (int r = 0; r < 4; r++) {
            float4 xv = xp[r];
            acc[4 * r + 0] += w * xv.x;
            acc[4 * r + 1] += w * xv.y;
            acc[4 * r + 2] += w * xv.z;
            acc[4 * r + 3] += w * xv.w;
        }
    }

    const int nbase = n0 + g * 16;
    if (m < 2) {
        __nv_bfloat16* Dh = (m == 0) ? g_Qh : g_Kh;
        __nv_bfloat16* Dl = (m == 0) ? g_Ql : g_Kl;
        #pragma unroll
        for (int i = 0; i < 16; i++) {
            float a = acc[i];
            __nv_bfloat16 h = __float2bfloat16(a);
            __nv_bfloat16 l = __float2bfloat16(a - __bfloat162float(h));
            size_t off = ((size_t)(b * 4096 + nbase + i)) * 64 + co;
            Dh[off] = h; Dl[off] = l;
        }
    } else {
        unsigned wh[8];
        #pragma unroll
        for (int i = 0; i < 8; i++) {
            __half2 h = __floats2half2_rn(acc[2 * i], acc[2 * i + 1]);
            wh[i] = *(unsigned*)&h;
        }
        size_t off = ((size_t)(b * 64 + co)) * 4096 + nbase;
        *(uint4*)(g_Vf + off)     = make_uint4(wh[0], wh[1], wh[2], wh[3]);
        *(uint4*)(g_Vf + off + 8) = make_uint4(wh[4], wh[5], wh[6], wh[7]);
    }
}

// ---------------------------------------------------------------------------
// Fused flash attention, two-pass:
//   pass 1: row maxima m_q via single-bf16 S (4 MMA units / tile-pair)
//   pass 2: S bf16 3-split (12) + softmax p=exp(s-m_q) in fp16 + PV fp16
//           single-term (4) -> 20 units vs 24 before.
// 256 thr = 8 warps = 4 q-warps x 2 k-groups; warp owns 32 q rows.
// smem: K [2][hi/lo][128x64 SW128] 64KB + V [2][64x128 fp16 SW256] 32KB + m 1KB.
// ---------------------------------------------------------------------------
#define OFF_K 0u
#define OFF_V 65536u
#define OFF_M 98304u
#define ATTN_SMEM 99328u

__global__ void __launch_bounds__(256, 1) attn_kernel(float* __restrict__ out)
{
    extern __shared__ __align__(1024) char smem[];
    const uint32_t sb = smem_u32(smem);
    const int tid  = threadIdx.x;
    const int lane = tid & 31;
    const int w    = tid >> 5;
    const int wq   = w & 3;        // q warp: rows [32wq, 32wq+32)
    const int grp  = w >> 2;       // k-split group 0/1
    const int b    = blockIdx.y;
    const int n0   = blockIdx.x * 128;

    const __nv_bfloat16* Qhg = g_Qh + ((size_t)(b * 4096 + n0)) * 64;
    const __nv_bfloat16* Qlg = g_Ql + ((size_t)(b * 4096 + n0)) * 64;
    const __nv_bfloat16* Khg = g_Kh + ((size_t)b * 4096) * 64;
    const __nv_bfloat16* Klg = g_Kl + ((size_t)b * 4096) * 64;
    const __half*        Vfg = g_Vf + (size_t)b * 64 * 4096;

    // ---- stage Q (hi at OFF_K, lo at +16KB), extract A-fragments ----
    for (int idx = tid; idx < 1024; idx += 256) {
        int row = idx >> 3, u = idx & 7;
        uint32_t d = SWZ128(row * 128 + u * 16);
        *(uint4*)(smem + OFF_K + d)         = *(const uint4*)(Qhg + row * 64 + u * 8);
        *(uint4*)(smem + OFF_K + d + 16384) = *(const uint4*)(Qlg + row * 64 + u * 8);
    }
    __syncthreads();

    uint32_t qh[2][4][4], ql[2][4][4];
    #pragma unroll
    for (int mi = 0; mi < 2; mi++) {
        int r = wq * 32 + mi * 16 + (lane & 15);
        #pragma unroll
        for (int ks = 0; ks < 4; ks++) {
            uint32_t a = sb + OFF_K + SWZ128(r * 128 + ks * 32 + (lane >> 4) * 16);
            ldsm4(qh[mi][ks][0], qh[mi][ks][1], qh[mi][ks][2], qh[mi][ks][3], a);
            ldsm4(ql[mi][ks][0], ql[mi][ks][1], ql[mi][ks][2], ql[mi][ks][3], a + 16384);
        }
    }
    __syncthreads();

    // ---- loaders ----
    auto loadKhi = [&](int it, int buf) {   // pass-1: K hi only
        uint32_t kb = sb + OFF_K + (uint32_t)buf * 32768u;
        const __nv_bfloat16* kh = Khg + (size_t)it * 128 * 64;
        for (int idx = tid; idx < 1024; idx += 256) {
            int row = idx >> 3, u = idx & 7;
            cpasync16(kb + SWZ128(row * 128 + u * 16), kh + row * 64 + u * 8);
        }
        CP_COMMIT();
    };
    auto loadKV = [&](int it, int buf) {    // pass-2: K hi+lo, V fp16
        uint32_t kb = sb + OFF_K + (uint32_t)buf * 32768u;
        uint32_t vb = sb + OFF_V + (uint32_t)buf * 16384u;
        const __nv_bfloat16* kh = Khg + (size_t)it * 128 * 64;
        const __nv_bfloat16* kl = Klg + (size_t)it * 128 * 64;
        for (int idx = tid; idx < 1024; idx += 256) {
            int row = idx >> 3, u = idx & 7;
            uint32_t d = kb + SWZ128(row * 128 + u * 16);
            cpasync16(d,         kh + row * 64 + u * 8);
            cpasync16(d + 16384, kl + row * 64 + u * 8);
        }
        for (int idx = tid; idx < 1024; idx += 256) {
            int c = idx >> 4, u = idx & 15;
            cpasync16(vb + SWZ256(c * 256 + u * 16), Vfg + (size_t)c * 4096 + it * 128 + u * 8);
        }
        CP_COMMIT();
    };

    const float NEG_INF = __int_as_float(0xff800000u);
    float mrow[2][2];

    // ================= PASS 1: exact row maxima =================
    {
        float mp[2][2] = {{NEG_INF, NEG_INF}, {NEG_INF, NEG_INF}};
        loadKhi(0, 0);
        loadKhi(1, 1);
        for (int it = 0; it < 32; it++) {
            if (it + 1 < 32) { CP_WAIT1(); } else { CP_WAIT0(); }
            __syncthreads();
            const uint32_t kb = sb + OFF_K + (uint32_t)(it & 1) * 32768u;
            #pragma unroll 1
            for (int kc = grp * 4; kc < grp * 4 + 4; kc++) {
                #pragma unroll
                for (int j = 0; j < 2; j++) {
                    const int nt = kc * 2 + j;
                    uint32_t bh[8];
                    const int br = nt * 8 + (lane & 7);
                    #pragma unroll
                    for (int ks2 = 0; ks2 < 2; ks2++) {
                        uint32_t a = kb + SWZ128(br * 128 + ks2 * 64 + (lane >> 3) * 16);
                        ldsm4(bh[4*ks2+0], bh[4*ks2+1], bh[4*ks2+2], bh[4*ks2+3], a);
                    }
                    #pragma unroll
                    for (int mi = 0; mi < 2; mi++) {
                        float s[4] = {0.f, 0.f, 0.f, 0.f};
                        #pragma unroll
                        for (int ks = 0; ks < 4; ks++)
                            mma16816(s, qh[mi][ks][0], qh[mi][ks][1], qh[mi][ks][2], qh[mi][ks][3],
                                     bh[2*ks], bh[2*ks+1]);
                        mp[mi][0] = fmaxf(mp[mi][0], fmaxf(s[0], s[1]));
                        mp[mi][1] = fmaxf(mp[mi][1], fmaxf(s[2], s[3]));
                    }
                }
            }
            __syncthreads();
            if (it + 2 < 32) loadKhi(it + 2, it & 1);
        }
        // reduce within quad (same rows), publish per-group, combine.
        #pragma unroll
        for (int mi = 0; mi < 2; mi++)
            #pragma unroll
            for (int h2 = 0; h2 < 2; h2++) {
                mp[mi][h2] = fmaxf(mp[mi][h2], __shfl_xor_sync(0xffffffffu, mp[mi][h2], 1));
                mp[mi][h2] = fmaxf(mp[mi][h2], __shfl_xor_sync(0xffffffffu, mp[mi][h2], 2));
            }
        float* mArr = (float*)(smem + OFF_M);   // [2 grp][128]
        if ((lane & 3) == 0) {
            #pragma unroll
            for (int mi = 0; mi < 2; mi++) {
                int r = wq * 32 + mi * 16 + (lane >> 2);
                mArr[grp * 128 + r]     = mp[mi][0];
                mArr[grp * 128 + r + 8] = mp[mi][1];
            }
        }
        __syncthreads();
        #pragma unroll
        for (int mi = 0; mi < 2; mi++) {
            int r = wq * 32 + mi * 16 + (lane >> 2);
            mrow[mi][0] = fmaxf(mArr[r],     mArr[128 + r]);
            mrow[mi][1] = fmaxf(mArr[r + 8], mArr[128 + r + 8]);
        }
    }

    // ================= PASS 2: attention =================
    loadKV(0, 0);
    loadKV(1, 1);

    float oacc[2][8][4];
    #pragma unroll
    for (int mi = 0; mi < 2; mi++)
        #pragma unroll
        for (int i = 0; i < 8; i++)
            #pragma unroll
            for (int j = 0; j < 4; j++) oacc[mi][i][j] = 0.0f;
    float lsum[2][2] = {{0.f, 0.f}, {0.f, 0.f}};

    for (int it = 0; it < 32; it++) {
        if (it + 1 < 32) { CP_WAIT1(); } else { CP_WAIT0(); }
        __syncthreads();

        const uint32_t kb = sb + OFF_K + (uint32_t)(it & 1) * 32768u;
        const uint32_t vb = sb + OFF_V + (uint32_t)(it & 1) * 16384u;

        // ---- S (bf16 3-split) for chunk kc ----
        auto S_step = [&](int kc, float sv[2][2][4]) {
            #pragma unroll
            for (int j = 0; j < 2; j++) {
                const int nt = kc * 2 + j;
                uint32_t bh[8], bl[8];
                const int br = nt * 8 + (lane & 7);
                #pragma unroll
                for (int ks2 = 0; ks2 < 2; ks2++) {
                    uint32_t a = kb + SWZ128(br * 128 + ks2 * 64 + (lane >> 3) * 16);
                    ldsm4(bh[4*ks2+0], bh[4*ks2+1], bh[4*ks2+2], bh[4*ks2+3], a);
                    ldsm4(bl[4*ks2+0], bl[4*ks2+1], bl[4*ks2+2], bl[4*ks2+3], a + 16384);
                }
                #pragma unroll
                for (int mi = 0; mi < 2; mi++) {
                    float sa[4] = {0.f, 0.f, 0.f, 0.f};
                    float sb2[4] = {0.f, 0.f, 0.f, 0.f};
                    float sc[4] = {0.f, 0.f, 0.f, 0.f};
                    #pragma unroll
                    for (int ks = 0; ks < 4; ks++) {
                        mma16816(sa,  qh[mi][ks][0], qh[mi][ks][1], qh[mi][ks][2], qh[mi][ks][3], bh[2*ks], bh[2*ks+1]);
                        mma16816(sb2, qh[mi][ks][0], qh[mi][ks][1], qh[mi][ks][2], qh[mi][ks][3], bl[2*ks], bl[2*ks+1]);
                        mma16816(sc,  ql[mi][ks][0], ql[mi][ks][1], ql[mi][ks][2], ql[mi][ks][3], bh[2*ks], bh[2*ks+1]);
                    }
                    #pragma unroll
                    for (int i = 0; i < 4; i++) sv[mi][j][i] = (sa[i] + sb2[i]) + sc[i];
                }
            }
        };

        // ---- PV (fp16 single) for chunk cp ----
        auto PV_step = [&](int cp, const uint32_t pa[2][4]) {
            #pragma unroll
            for (int cnp = 0; cnp < 4; cnp++) {
                const int row = cnp * 16 + (lane >> 4) * 8 + (lane & 7);
                const int chunk = cp * 2 + ((lane >> 3) & 1);
                uint32_t a = vb + SWZ256(row * 256 + chunk * 16);
                uint32_t vh[4];
                ldsm4(vh[0], vh[1], vh[2], vh[3], a);
                #pragma unroll
                for (int mi = 0; mi < 2; mi++) {
                    mma16816h(oacc[mi][2*cnp],   pa[mi][0], pa[mi][1], pa[mi][2], pa[mi][3], vh[0], vh[1]);
                    mma16816h(oacc[mi][2*cnp+1], pa[mi][0], pa[mi][1], pa[mi][2], pa[mi][3], vh[2], vh[3]);
                }
            }
        };

        // ---- softmax: p = exp(s - m_row), fp16; lsum from rounded p ----
        auto softmax_step = [&](const float sv[2][2][4], uint32_t pa[2][4]) {
            #pragma unroll
            for (int mi = 0; mi < 2; mi++) {
                #pragma unroll
                for (int j = 0; j < 2; j++) {
                    float p0 = __expf(sv[mi][j][0] - mrow[mi][0]);
                    float p1 = __expf(sv[mi][j][1] - mrow[mi][0]);
                    float p2 = __expf(sv[mi][j][2] - mrow[mi][1]);
                    float p3 = __expf(sv[mi][j][3] - mrow[mi][1]);
                    __half2 h01 = __floats2half2_rn(p0, p1);
                    __half2 h23 = __floats2half2_rn(p2, p3);
                    float2 f01 = __half22float2(h01);
                    float2 f23 = __half22float2(h23);
                    lsum[mi][0] += f01.x + f01.y;
                    lsum[mi][1] += f23.x + f23.y;
                    pa[mi][2*j]   = *(uint32_t*)&h01;
                    pa[mi][2*j+1] = *(uint32_t*)&h23;
                }
            }
        };

        // ---- this group's 4 chunks, pipelined ----
        const int kc0 = grp * 4;
        uint32_t pa[2][4];
        {
            float sv[2][2][4];
            S_step(kc0, sv);
            softmax_step(sv, pa);
        }
        #pragma unroll 1
        for (int kc = kc0 + 1; kc < kc0 + 4; kc++) {
            float sv[2][2][4];
            S_step(kc, sv);
            PV_step(kc - 1, pa);
            softmax_step(sv, pa);
        }
        PV_step(kc0 + 3, pa);

        __syncthreads();
        if (it + 2 < 32) loadKV(it + 2, it & 1);
    }

    // ---- epilogue: merge group partials, normalize, store (B,C,N) ----
    #pragma unroll
    for (int mi = 0; mi < 2; mi++)
        #pragma unroll
        for (int h2 = 0; h2 < 2; h2++) {
            lsum[mi][h2] += __shfl_xor_sync(0xffffffffu, lsum[mi][h2], 1);
            lsum[mi][h2] += __shfl_xor_sync(0xffffffffu, lsum[mi][h2], 2);
        }

    float* pO = (float*)smem;                  // [64c][128q] 32KB
    float* pL = (float*)(smem + 65536);        // [128]

    if (grp == 1) {
        #pragma unroll
        for (int mi = 0; mi < 2; mi++) {
            const int q0 = wq * 32 + mi * 16 + (lane >> 2);
            #pragma unroll
            for (int cn = 0; cn < 8; cn++) {
                const int c = cn * 8 + 2 * (lane & 3);
                pO[c * 128 + q0]           = oacc[mi][cn][0];
                pO[(c + 1) * 128 + q0]     = oacc[mi][cn][1];
                pO[c * 128 + q0 + 8]       = oacc[mi][cn][2];
                pO[(c + 1) * 128 + q0 + 8] = oacc[mi][cn][3];
            }
            if ((lane & 3) == 0) { pL[q0] = lsum[mi][0]; pL[q0 + 8] = lsum[mi][1]; }
        }
    }
    __syncthreads();
    if (grp == 0) {
        #pragma unroll
        for (int mi = 0; mi < 2; mi++) {
            const int q0 = wq * 32 + mi * 16 + (lane >> 2);
            const float inv0 = 1.0f / (lsum[mi][0] + pL[q0]);
            const float inv1 = 1.0f / (lsum[mi][1] + pL[q0 + 8]);
            #pragma unroll
            for (int cn = 0; cn < 8; cn++) {
                const int c = cn * 8 + 2 * (lane & 3);
                pO[c * 128 + q0]           = (oacc[mi][cn][0] + pO[c * 128 + q0]) * inv0;
                pO[(c + 1) * 128 + q0]     = (oacc[mi][cn][1] + pO[(c + 1) * 128 + q0]) * inv0;
                pO[c * 128 + q0 + 8]       = (oacc[mi][cn][2] + pO[c * 128 + q0 + 8]) * inv1;
                pO[(c + 1) * 128 + q0 + 8] = (oacc[mi][cn][3] + pO[(c + 1) * 128 + q0 + 8]) * inv1;
            }
        }
    }
    __syncthreads();

    float* outb = out + (size_t)b * 64 * 4096;
    for (int idx = tid; idx < 8192; idx += 256) {
        int c = idx >> 7, qq = idx & 127;
        outb[(size_t)c * 4096 + n0 + qq] = pO[idx];
    }
}

extern "C" void kernel_launch(void* const* d_in, const int* in_sizes, int n_in,
                              void* d_out, int out_size)
{
    const float* x  = (const float*)d_in[0];
    const float* Wq = (const float*)d_in[1];
    const float* bq = (const float*)d_in[2];
    const float* Wk = (const float*)d_in[3];
    const float* bk = (const float*)d_in[4];
    const float* Wv = (const float*)d_in[5];
    const float* bv = (const float*)d_in[6];
    float* out = (float*)d_out;

    qkv_kernel<<<dim3(64, NB, 3), 256>>>(x, Wq, bq, Wk, bk, Wv, bv);

    cudaFuncSetAttribute(attn_kernel, cudaFuncAttributeMaxDynamicSharedMemorySize, ATTN_SMEM);
    attn_kernel<<<dim3(32, NB), 256, ATTN_SMEM>>>(out);
}

// round 15
// speedup vs baseline: 1.1685x; 1.0518x over previous
#include <cuda_runtime.h>
#include <cuda_bf16.h>
#include <cuda_fp16.h>
#include <stdint.h>

#define NB 4
#define NC 64
#define NN 4096

// bf16 hi/lo split Q/K + fp16 single V, MMA-native layouts.
__device__ __nv_bfloat16 g_Qh[NB*NN*NC];   // (B, N, C)
__device__ __nv_bfloat16 g_Ql[NB*NN*NC];
__device__ __nv_bfloat16 g_Kh[NB*NN*NC];   // (B, N, C)
__device__ __nv_bfloat16 g_Kl[NB*NN*NC];
__device__ __half        g_Vf[NB*NC*NN];   // (B, C, N)

// ---------------------------------------------------------------------------
// Arch-agnostic tensor-core helpers (sm_80+ PTX only: ldmatrix / mma / cp.async)
// ---------------------------------------------------------------------------
__device__ __forceinline__ uint32_t smem_u32(const void* p) {
    uint32_t a;
    asm("{ .reg .u64 t; cvta.to.shared.u64 t, %1; cvt.u32.u64 %0, t; }" : "=r"(a) : "l"(p));
    return a;
}

#define SWZ128(x) ((uint32_t)(x) ^ ((((uint32_t)(x)) >> 3) & 0x70u))
#define SWZ256(x) ((uint32_t)(x) ^ ((((uint32_t)(x)) >> 4) & 0x70u))

__device__ __forceinline__ void ldsm4(uint32_t &r0, uint32_t &r1, uint32_t &r2, uint32_t &r3,
                                      uint32_t a) {
    asm volatile("ldmatrix.sync.aligned.m8n8.x4.shared.b16 {%0,%1,%2,%3}, [%4];"
                 : "=r"(r0), "=r"(r1), "=r"(r2), "=r"(r3) : "r"(a));
}

__device__ __forceinline__ void mma16816(float c[4],
                                         uint32_t a0, uint32_t a1, uint32_t a2, uint32_t a3,
                                         uint32_t b0, uint32_t b1) {
    asm volatile("mma.sync.aligned.m16n8k16.row.col.f32.bf16.bf16.f32 "
                 "{%0,%1,%2,%3}, {%4,%5,%6,%7}, {%8,%9}, {%0,%1,%2,%3};"
                 : "+f"(c[0]), "+f"(c[1]), "+f"(c[2]), "+f"(c[3])
                 : "r"(a0), "r"(a1), "r"(a2), "r"(a3), "r"(b0), "r"(b1));
}

__device__ __forceinline__ void mma16816h(float c[4],
                                          uint32_t a0, uint32_t a1, uint32_t a2, uint32_t a3,
                                          uint32_t b0, uint32_t b1) {
    asm volatile("mma.sync.aligned.m16n8k16.row.col.f32.f16.f16.f32 "
                 "{%0,%1,%2,%3}, {%4,%5,%6,%7}, {%8,%9}, {%0,%1,%2,%3};"
                 : "+f"(c[0]), "+f"(c[1]), "+f"(c[2]), "+f"(c[3])
                 : "r"(a0), "r"(a1), "r"(a2), "r"(a3), "r"(b0), "r"(b1));
}

__device__ __forceinline__ void cpasync16(uint32_t s, const void* g) {
    asm volatile("cp.async.cg.shared.global [%0], [%1], 16;"
                 :: "r"(s), "l"(__cvta_generic_to_global(g)) : "memory");
}
#define CP_COMMIT() asm volatile("cp.async.commit_group;" ::: "memory")
#define CP_WAIT1()  asm volatile("cp.async.wait_group 1;" ::: "memory")
#define CP_WAIT0()  asm volatile("cp.async.wait_group 0;" ::: "memory")

// ---------------------------------------------------------------------------
// QKV projection: Q/K bf16 hi/lo, V fp16 single; one matrix per blockIdx.z.
// ---------------------------------------------------------------------------
__global__ __launch_bounds__(256) void qkv_kernel(
    const float* __restrict__ x,
    const float* __restrict__ Wq, const float* __restrict__ bq,
    const float* __restrict__ Wk, const float* __restrict__ bk,
    const float* __restrict__ Wv, const float* __restrict__ bv)
{
    __shared__ float xs[64 * 64];
    __shared__ float wts[64 * 65];

    const int tid = threadIdx.x;
    const int b = blockIdx.y;
    const int n0 = blockIdx.x * 64;
    const int m  = blockIdx.z;

    const float* W = (m == 0) ? Wq : (m == 1) ? Wk : Wv;
    const float* bias_v = (m == 0) ? bq : (m == 1) ? bk : bv;

    for (int idx = tid; idx < 4096; idx += 256) {
        int c = idx >> 6, nn = idx & 63;
        xs[idx] = x[(size_t)(b * 64 + c) * 4096 + n0 + nn];
    }
    for (int idx = tid; idx < 4096; idx += 256)
        wts[(idx & 63) * 65 + (idx >> 6)] = W[idx];
    __syncthreads();

    const int co = tid & 63;
    const int g  = tid >> 6;

    float acc[16];
    const float bias = bias_v[co];
    #pragma unroll
    for (int i = 0; i < 16; i++) acc[i] = bias;

    #pragma unroll 4
    for (int c = 0; c < 64; c++) {
        float w = wts[c * 65 + co];
        const float4* xp = (const float4*)(xs + c * 64 + g * 16);
        #pragma unroll
        for (int r = 0; r < 4; r++) {
            float4 xv = xp[r];
            acc[4 * r + 0] += w * xv.x;
            acc[4 * r + 1] += w * xv.y;
            acc[4 * r + 2] += w * xv.z;
            acc[4 * r + 3] += w * xv.w;
        }
    }

    const int nbase = n0 + g * 16;
    if (m < 2) {
        __nv_bfloat16* Dh = (m == 0) ? g_Qh : g_Kh;
        __nv_bfloat16* Dl = (m == 0) ? g_Ql : g_Kl;
        #pragma unroll
        for (int i = 0; i < 16; i++) {
            float a = acc[i];
            __nv_bfloat16 h = __float2bfloat16(a);
            __nv_bfloat16 l = __float2bfloat16(a - __bfloat162float(h));
            size_t off = ((size_t)(b * 4096 + nbase + i)) * 64 + co;
            Dh[off] = h; Dl[off] = l;
        }
    } else {
        unsigned wh[8];
        #pragma unroll
        for (int i = 0; i < 8; i++) {
            __half2 h = __floats2half2_rn(acc[2 * i], acc[2 * i + 1]);
            wh[i] = *(unsigned*)&h;
        }
        size_t off = ((size_t)(b * 64 + co)) * 4096 + nbase;
        *(uint4*)(g_Vf + off)     = make_uint4(wh[0], wh[1], wh[2], wh[3]);
        *(uint4*)(g_Vf + off + 8) = make_uint4(wh[4], wh[5], wh[6], wh[7]);
    }
}

// ---------------------------------------------------------------------------
// Fused flash attention, single pass with ONLINE row max (FA2-style):
//   S bf16 3-split (12 units) -> per-chunk row max (quad shfl) -> running max
//   -> p = exp(s - m_run) in fp16 (always <= 1, in range) -> PV fp16 (4 units)
//   O rescaled by alpha = exp(m_old - m_new), lazily (skipped when alpha==1).
// 256 thr = 8 warps = 4 q-warps x 2 k-groups; warp owns 32 q rows.
// Group partials (O, l, m) merged max-aware in the epilogue.
// smem: K [2][hi/lo][128x64 SW128] 64KB + V [2][64x128 fp16 SW256] 32KB + merge 1KB.
// ---------------------------------------------------------------------------
#define OFF_K 0u
#define OFF_V 65536u
#define OFF_M 98304u
#define ATTN_SMEM 99328u

__global__ void __launch_bounds__(256, 1) attn_kernel(float* __restrict__ out)
{
    extern __shared__ __align__(1024) char smem[];
    const uint32_t sb = smem_u32(smem);
    const int tid  = threadIdx.x;
    const int lane = tid & 31;
    const int w    = tid >> 5;
    const int wq   = w & 3;        // q warp: rows [32wq, 32wq+32)
    const int grp  = w >> 2;       // k-split group 0/1
    const int b    = blockIdx.y;
    const int n0   = blockIdx.x * 128;

    const __nv_bfloat16* Qhg = g_Qh + ((size_t)(b * 4096 + n0)) * 64;
    const __nv_bfloat16* Qlg = g_Ql + ((size_t)(b * 4096 + n0)) * 64;
    const __nv_bfloat16* Khg = g_Kh + ((size_t)b * 4096) * 64;
    const __nv_bfloat16* Klg = g_Kl + ((size_t)b * 4096) * 64;
    const __half*        Vfg = g_Vf + (size_t)b * 64 * 4096;

    // ---- stage Q (hi at OFF_K, lo at +16KB), extract A-fragments ----
    for (int idx = tid; idx < 1024; idx += 256) {
        int row = idx >> 3, u = idx & 7;
        uint32_t d = SWZ128(row * 128 + u * 16);
        *(uint4*)(smem + OFF_K + d)         = *(const uint4*)(Qhg + row * 64 + u * 8);
        *(uint4*)(smem + OFF_K + d + 16384) = *(const uint4*)(Qlg + row * 64 + u * 8);
    }
    __syncthreads();

    uint32_t qh[2][4][4], ql[2][4][4];
    #pragma unroll
    for (int mi = 0; mi < 2; mi++) {
        int r = wq * 32 + mi * 16 + (lane & 15);
        #pragma unroll
        for (int ks = 0; ks < 4; ks++) {
            uint32_t a = sb + OFF_K + SWZ128(r * 128 + ks * 32 + (lane >> 4) * 16);
            ldsm4(qh[mi][ks][0], qh[mi][ks][1], qh[mi][ks][2], qh[mi][ks][3], a);
            ldsm4(ql[mi][ks][0], ql[mi][ks][1], ql[mi][ks][2], ql[mi][ks][3], a + 16384);
        }
    }
    __syncthreads();

    // ---- async tile loader: K hi+lo, V fp16 ----
    auto loadKV = [&](int it, int buf) {
        uint32_t kb = sb + OFF_K + (uint32_t)buf * 32768u;
        uint32_t vb = sb + OFF_V + (uint32_t)buf * 16384u;
        const __nv_bfloat16* kh = Khg + (size_t)it * 128 * 64;
        const __nv_bfloat16* kl = Klg + (size_t)it * 128 * 64;
        for (int idx = tid; idx < 1024; idx += 256) {
            int row = idx >> 3, u = idx & 7;
            uint32_t d = kb + SWZ128(row * 128 + u * 16);
            cpasync16(d,         kh + row * 64 + u * 8);
            cpasync16(d + 16384, kl + row * 64 + u * 8);
        }
        for (int idx = tid; idx < 1024; idx += 256) {
            int c = idx >> 4, u = idx & 15;
            cpasync16(vb + SWZ256(c * 256 + u * 16), Vfg + (size_t)c * 4096 + it * 128 + u * 8);
        }
        CP_COMMIT();
    };

    loadKV(0, 0);
    loadKV(1, 1);

    const float NEG_INF = __int_as_float(0xff800000u);
    float oacc[2][8][4];
    #pragma unroll
    for (int mi = 0; mi < 2; mi++)
        #pragma unroll
        for (int i = 0; i < 8; i++)
            #pragma unroll
            for (int j = 0; j < 4; j++) oacc[mi][i][j] = 0.0f;
    float lsum[2][2] = {{0.f, 0.f}, {0.f, 0.f}};
    float mrow[2][2] = {{NEG_INF, NEG_INF}, {NEG_INF, NEG_INF}};

    for (int it = 0; it < 32; it++) {
        if (it + 1 < 32) { CP_WAIT1(); } else { CP_WAIT0(); }
        __syncthreads();

        const uint32_t kb = sb + OFF_K + (uint32_t)(it & 1) * 32768u;
        const uint32_t vb = sb + OFF_V + (uint32_t)(it & 1) * 16384u;

        // ---- S (bf16 3-split) for chunk kc ----
        auto S_step = [&](int kc, float sv[2][2][4]) {
            #pragma unroll
            for (int j = 0; j < 2; j++) {
                const int nt = kc * 2 + j;
                uint32_t bh[8], bl[8];
                const int br = nt * 8 + (lane & 7);
                #pragma unroll
                for (int ks2 = 0; ks2 < 2; ks2++) {
                    uint32_t a = kb + SWZ128(br * 128 + ks2 * 64 + (lane >> 3) * 16);
                    ldsm4(bh[4*ks2+0], bh[4*ks2+1], bh[4*ks2+2], bh[4*ks2+3], a);
                    ldsm4(bl[4*ks2+0], bl[4*ks2+1], bl[4*ks2+2], bl[4*ks2+3], a + 16384);
                }
                #pragma unroll
                for (int mi = 0; mi < 2; mi++) {
                    float sa[4] = {0.f, 0.f, 0.f, 0.f};
                    float sb2[4] = {0.f, 0.f, 0.f, 0.f};
                    float sc[4] = {0.f, 0.f, 0.f, 0.f};
                    #pragma unroll
                    for (int ks = 0; ks < 4; ks++) {
                        mma16816(sa,  qh[mi][ks][0], qh[mi][ks][1], qh[mi][ks][2], qh[mi][ks][3], bh[2*ks], bh[2*ks+1]);
                        mma16816(sb2, qh[mi][ks][0], qh[mi][ks][1], qh[mi][ks][2], qh[mi][ks][3], bl[2*ks], bl[2*ks+1]);
                        mma16816(sc,  ql[mi][ks][0], ql[mi][ks][1], ql[mi][ks][2], ql[mi][ks][3], bh[2*ks], bh[2*ks+1]);
                    }
                    #pragma unroll
                    for (int i = 0; i < 4; i++) sv[mi][j][i] = (sa[i] + sb2[i]) + sc[i];
                }
            }
        };

        // ---- PV (fp16 single) for chunk cp ----
        auto PV_step = [&](int cp, const uint32_t pa[2][4]) {
            #pragma unroll
            for (int cnp = 0; cnp < 4; cnp++) {
                const int row = cnp * 16 + (lane >> 4) * 8 + (lane & 7);
                const int chunk = cp * 2 + ((lane >> 3) & 1);
                uint32_t a = vb + SWZ256(row * 256 + chunk * 16);
                uint32_t vh[4];
                ldsm4(vh[0], vh[1], vh[2], vh[3], a);
                #pragma unroll
                for (int mi = 0; mi < 2; mi++) {
                    mma16816h(oacc[mi][2*cnp],   pa[mi][0], pa[mi][1], pa[mi][2], pa[mi][3], vh[0], vh[1]);
                    mma16816h(oacc[mi][2*cnp+1], pa[mi][0], pa[mi][1], pa[mi][2], pa[mi][3], vh[2], vh[3]);
                }
            }
        };

        // ---- online softmax: update running max, rescale O lazily, emit p ----
        auto softmax_step = [&](const float sv[2][2][4], uint32_t pa[2][4]) {
            #pragma unroll
            for (int mi = 0; mi < 2; mi++) {
                float t0 = fmaxf(fmaxf(sv[mi][0][0], sv[mi][0][1]), fmaxf(sv[mi][1][0], sv[mi][1][1]));
                float t1 = fmaxf(fmaxf(sv[mi][0][2], sv[mi][0][3]), fmaxf(sv[mi][1][2], sv[mi][1][3]));
                t0 = fmaxf(t0, __shfl_xor_sync(0xffffffffu, t0, 1));
                t0 = fmaxf(t0, __shfl_xor_sync(0xffffffffu, t0, 2));
                t1 = fmaxf(t1, __shfl_xor_sync(0xffffffffu, t1, 1));
                t1 = fmaxf(t1, __shfl_xor_sync(0xffffffffu, t1, 2));

                float m0 = fmaxf(mrow[mi][0], t0);
                float m1 = fmaxf(mrow[mi][1], t1);
                float a0 = __expf(mrow[mi][0] - m0);   // 1 if max unchanged
                float a1 = __expf(mrow[mi][1] - m1);
                mrow[mi][0] = m0;
                mrow[mi][1] = m1;

                if (a0 < 1.0f || a1 < 1.0f) {          // lazy rescale (rare)
                    lsum[mi][0] *= a0;
                    lsum[mi][1] *= a1;
                    #pragma unroll
                    for (int cn = 0; cn < 8; cn++) {
                        oacc[mi][cn][0] *= a0;
                        oacc[mi][cn][1] *= a0;
                        oacc[mi][cn][2] *= a1;
                        oacc[mi][cn][3] *= a1;
                    }
                }

                #pragma unroll
                for (int j = 0; j < 2; j++) {
                    float p0 = __expf(sv[mi][j][0] - m0);
                    float p1 = __expf(sv[mi][j][1] - m0);
                    float p2 = __expf(sv[mi][j][2] - m1);
                    float p3 = __expf(sv[mi][j][3] - m1);
                    __half2 h01 = __floats2half2_rn(p0, p1);
                    __half2 h23 = __floats2half2_rn(p2, p3);
                    float2 f01 = __half22float2(h01);
                    float2 f23 = __half22float2(h23);
                    lsum[mi][0] += f01.x + f01.y;
                    lsum[mi][1] += f23.x + f23.y;
                    pa[mi][2*j]   = *(uint32_t*)&h01;
                    pa[mi][2*j+1] = *(uint32_t*)&h23;
                }
            }
        };

        // ---- this group's 4 chunks, pipelined ----
        const int kc0 = grp * 4;
        uint32_t pa[2][4];
        {
            float sv[2][2][4];
            S_step(kc0, sv);
            softmax_step(sv, pa);
        }
        #pragma unroll 1
        for (int kc = kc0 + 1; kc < kc0 + 4; kc++) {
            float sv[2][2][4];
            S_step(kc, sv);
            PV_step(kc - 1, pa);
            softmax_step(sv, pa);
        }
        PV_step(kc0 + 3, pa);

        __syncthreads();
        if (it + 2 < 32) loadKV(it + 2, it & 1);
    }

    // ---- epilogue: quad-reduce lsum, max-aware group merge, store ----
    #pragma unroll
    for (int mi = 0; mi < 2; mi++)
        #pragma unroll
        for (int h2 = 0; h2 < 2; h2++) {
            lsum[mi][h2] += __shfl_xor_sync(0xffffffffu, lsum[mi][h2], 1);
            lsum[mi][h2] += __shfl_xor_sync(0xffffffffu, lsum[mi][h2], 2);
        }

    float* pO = (float*)smem;                    // [64c][128q] 32KB
    float* pLl = (float*)(smem + OFF_M);         // [128] group-1 lsum
    float* pLm = (float*)(smem + OFF_M + 512);   // [128] group-1 max

    if (grp == 1) {
        #pragma unroll
        for (int mi = 0; mi < 2; mi++) {
            const int q0 = wq * 32 + mi * 16 + (lane >> 2);
            #pragma unroll
            for (int cn = 0; cn < 8; cn++) {
                const int c = cn * 8 + 2 * (lane & 3);
                pO[c * 128 + q0]           = oacc[mi][cn][0];
                pO[(c + 1) * 128 + q0]     = oacc[mi][cn][1];
                pO[c * 128 + q0 + 8]       = oacc[mi][cn][2];
                pO[(c + 1) * 128 + q0 + 8] = oacc[mi][cn][3];
            }
            if ((lane & 3) == 0) {
                pLl[q0]     = lsum[mi][0];  pLl[q0 + 8] = lsum[mi][1];
                pLm[q0]     = mrow[mi][0];  pLm[q0 + 8] = mrow[mi][1];
            }
        }
    }
    __syncthreads();
    if (grp == 0) {
        #pragma unroll
        for (int mi = 0; mi < 2; mi++) {
            const int q0 = wq * 32 + mi * 16 + (lane >> 2);
            #pragma unroll
            for (int h2 = 0; h2 < 2; h2++) {
                const int qq = q0 + 8 * h2;
                float m1v = pLm[qq], l1v = pLl[qq];
                float M = fmaxf(mrow[mi][h2], m1v);
                float f0 = __expf(mrow[mi][h2] - M);
                float f1 = __expf(m1v - M);
                float inv = 1.0f / (lsum[mi][h2] * f0 + l1v * f1);
                float g0 = f0 * inv, g1 = f1 * inv;
                #pragma unroll
                for (int cn = 0; cn < 8; cn++) {
                    const int c = cn * 8 + 2 * (lane & 3);
                    pO[c * 128 + qq]       = oacc[mi][cn][2*h2]   * g0 + pO[c * 128 + qq]       * g1;
                    pO[(c + 1) * 128 + qq] = oacc[mi][cn][2*h2+1] * g0 + pO[(c + 1) * 128 + qq] * g1;
                }
            }
        }
    }
    __syncthreads();

    float* outb = out + (size_t)b * 64 * 4096;
    for (int idx = tid; idx < 8192; idx += 256) {
        int c = idx >> 7, qq = idx & 127;
        outb[(size_t)c * 4096 + n0 + qq] = pO[idx];
    }
}

extern "C" void kernel_launch(void* const* d_in, const int* in_sizes, int n_in,
                              void* d_out, int out_size)
{
    const float* x  = (const float*)d_in[0];
    const float* Wq = (const float*)d_in[1];
    const float* bq = (const float*)d_in[2];
    const float* Wk = (const float*)d_in[3];
    const float* bk = (const float*)d_in[4];
    const float* Wv = (const float*)d_in[5];
    const float* bv = (const float*)d_in[6];
    float* out = (float*)d_out;

    qkv_kernel<<<dim3(64, NB, 3), 256>>>(x, Wq, bq, Wk, bk, Wv, bv);

    cudaFuncSetAttribute(attn_kernel, cudaFuncAttributeMaxDynamicSharedMemorySize, ATTN_SMEM);
    attn_kernel<<<dim3(32, NB), 256, ATTN_SMEM>>>(out);
}

// round 16
// speedup vs baseline: 1.2021x; 1.0287x over previous
#include <cuda_runtime.h>
#include <cuda_bf16.h>
#include <cuda_fp16.h>
#include <stdint.h>

#define NB 4
#define NC 64
#define NN 4096

// bf16 hi/lo split Q/K + fp16 single V, MMA-native layouts.
__device__ __nv_bfloat16 g_Qh[NB*NN*NC];   // (B, N, C)
__device__ __nv_bfloat16 g_Ql[NB*NN*NC];
__device__ __nv_bfloat16 g_Kh[NB*NN*NC];   // (B, N, C)
__device__ __nv_bfloat16 g_Kl[NB*NN*NC];
__device__ __half        g_Vf[NB*NC*NN];   // (B, C, N)

// ---------------------------------------------------------------------------
// Arch-agnostic tensor-core helpers (sm_80+ PTX only: ldmatrix / mma / cp.async)
// ---------------------------------------------------------------------------
__device__ __forceinline__ uint32_t smem_u32(const void* p) {
    uint32_t a;
    asm("{ .reg .u64 t; cvta.to.shared.u64 t, %1; cvt.u32.u64 %0, t; }" : "=r"(a) : "l"(p));
    return a;
}

#define SWZ128(x) ((uint32_t)(x) ^ ((((uint32_t)(x)) >> 3) & 0x70u))
#define SWZ256(x) ((uint32_t)(x) ^ ((((uint32_t)(x)) >> 4) & 0x70u))

__device__ __forceinline__ void ldsm4(uint32_t &r0, uint32_t &r1, uint32_t &r2, uint32_t &r3,
                                      uint32_t a) {
    asm volatile("ldmatrix.sync.aligned.m8n8.x4.shared.b16 {%0,%1,%2,%3}, [%4];"
                 : "=r"(r0), "=r"(r1), "=r"(r2), "=r"(r3) : "r"(a));
}

__device__ __forceinline__ void mma16816(float c[4],
                                         uint32_t a0, uint32_t a1, uint32_t a2, uint32_t a3,
                                         uint32_t b0, uint32_t b1) {
    asm volatile("mma.sync.aligned.m16n8k16.row.col.f32.bf16.bf16.f32 "
                 "{%0,%1,%2,%3}, {%4,%5,%6,%7}, {%8,%9}, {%0,%1,%2,%3};"
                 : "+f"(c[0]), "+f"(c[1]), "+f"(c[2]), "+f"(c[3])
                 : "r"(a0), "r"(a1), "r"(a2), "r"(a3), "r"(b0), "r"(b1));
}

__device__ __forceinline__ void mma16816h(float c[4],
                                          uint32_t a0, uint32_t a1, uint32_t a2, uint32_t a3,
                                          uint32_t b0, uint32_t b1) {
    asm volatile("mma.sync.aligned.m16n8k16.row.col.f32.f16.f16.f32 "
                 "{%0,%1,%2,%3}, {%4,%5,%6,%7}, {%8,%9}, {%0,%1,%2,%3};"
                 : "+f"(c[0]), "+f"(c[1]), "+f"(c[2]), "+f"(c[3])
                 : "r"(a0), "r"(a1), "r"(a2), "r"(a3), "r"(b0), "r"(b1));
}

__device__ __forceinline__ void cpasync16(uint32_t s, const void* g) {
    asm volatile("cp.async.cg.shared.global [%0], [%1], 16;"
                 :: "r"(s), "l"(__cvta_generic_to_global(g)) : "memory");
}
#define CP_COMMIT() asm volatile("cp.async.commit_group;" ::: "memory")
#define CP_WAIT1()  asm volatile("cp.async.wait_group 1;" ::: "memory")
#define CP_WAIT0()  asm volatile("cp.async.wait_group 0;" ::: "memory")

// ---------------------------------------------------------------------------
// QKV projection: Q/K bf16 hi/lo, V fp16 single; one matrix per blockIdx.z.
// ---------------------------------------------------------------------------
__global__ __launch_bounds__(256) void qkv_kernel(
    const float* __restrict__ x,
    const float* __restrict__ Wq, const float* __restrict__ bq,
    const float* __restrict__ Wk, const float* __restrict__ bk,
    const float* __restrict__ Wv, const float* __restrict__ bv)
{
    __shared__ float xs[64 * 64];
    __shared__ float wts[64 * 65];

    const int tid = threadIdx.x;
    const int b = blockIdx.y;
    const int n0 = blockIdx.x * 64;
    const int m  = blockIdx.z;

    const float* W = (m == 0) ? Wq : (m == 1) ? Wk : Wv;
    const float* bias_v = (m == 0) ? bq : (m == 1) ? bk : bv;

    for (int idx = tid; idx < 4096; idx += 256) {
        int c = idx >> 6, nn = idx & 63;
        xs[idx] = x[(size_t)(b * 64 + c) * 4096 + n0 + nn];
    }
    for (int idx = tid; idx < 4096; idx += 256)
        wts[(idx & 63) * 65 + (idx >> 6)] = W[idx];
    __syncthreads();

    const int co = tid & 63;
    const int g  = tid >> 6;

    float acc[16];
    const float bias = bias_v[co];
    #pragma unroll
    for (int i = 0; i < 16; i++) acc[i] = bias;

    #pragma unroll 4
    for (int c = 0; c < 64; c++) {
        float w = wts[c * 65 + co];
        const float4* xp = (const float4*)(xs + c * 64 + g * 16);
        #pragma unroll
        for (int r = 0; r < 4; r++) {
            float4 xv = xp[r];
            acc[4 * r + 0] += w * xv.x;
            acc[4 * r + 1] += w * xv.y;
            acc[4 * r + 2] += w * xv.z;
            acc[4 * r + 3] += w * xv.w;
        }
    }

    const int nbase = n0 + g * 16;
    if (m < 2) {
        __nv_bfloat16* Dh = (m == 0) ? g_Qh : g_Kh;
        __nv_bfloat16* Dl = (m == 0) ? g_Ql : g_Kl;
        #pragma unroll
        for (int i = 0; i < 16; i++) {
            float a = acc[i];
            __nv_bfloat16 h = __float2bfloat16(a);
            __nv_bfloat16 l = __float2bfloat16(a - __bfloat162float(h));
            size_t off = ((size_t)(b * 4096 + nbase + i)) * 64 + co;
            Dh[off] = h; Dl[off] = l;
        }
    } else {
        unsigned wh[8];
        #pragma unroll
        for (int i = 0; i < 8; i++) {
            __half2 h = __floats2half2_rn(acc[2 * i], acc[2 * i + 1]);
            wh[i] = *(unsigned*)&h;
        }
        size_t off = ((size_t)(b * 64 + co)) * 4096 + nbase;
        *(uint4*)(g_Vf + off)     = make_uint4(wh[0], wh[1], wh[2], wh[3]);
        *(uint4*)(g_Vf + off + 8) = make_uint4(wh[4], wh[5], wh[6], wh[7]);
    }
}

// ---------------------------------------------------------------------------
// Fused flash attention, single pass, online row max (FA2-style), fp16 PV.
// 512 thr = 16 warps = 8 q-warps x 2 k-groups; warp owns 16 q rows.
// Group g does chunks [4g, 4g+4) of each 128-key tile against shared K/V smem.
// -> 4 warps/SMSP (occ 25%) to fill issue slots now that the kernel is
// latency-bound in non-MMA work (R15: tensor 42%, issue 40%).
// Group partials (O, l, m) merged max-aware in the epilogue.
// smem: K [2][hi/lo][128x64 SW128] 64KB + V [2][64x128 fp16 SW256] 32KB + merge 1KB.
// ---------------------------------------------------------------------------
#define OFF_K 0u
#define OFF_V 65536u
#define OFF_M 98304u
#define ATTN_SMEM 99328u

__global__ void __launch_bounds__(512, 1) attn_kernel(float* __restrict__ out)
{
    extern __shared__ __align__(1024) char smem[];
    const uint32_t sb = smem_u32(smem);
    const int tid  = threadIdx.x;
    const int lane = tid & 31;
    const int w    = tid >> 5;
    const int wq   = w & 7;        // q warp: rows [16wq, 16wq+16)
    const int grp  = w >> 3;       // k-split group 0/1
    const int b    = blockIdx.y;
    const int n0   = blockIdx.x * 128;

    const __nv_bfloat16* Qhg = g_Qh + ((size_t)(b * 4096 + n0)) * 64;
    const __nv_bfloat16* Qlg = g_Ql + ((size_t)(b * 4096 + n0)) * 64;
    const __nv_bfloat16* Khg = g_Kh + ((size_t)b * 4096) * 64;
    const __nv_bfloat16* Klg = g_Kl + ((size_t)b * 4096) * 64;
    const __half*        Vfg = g_Vf + (size_t)b * 64 * 4096;

    // ---- stage Q (hi at OFF_K, lo at +16KB), extract A-fragments ----
    for (int idx = tid; idx < 1024; idx += 512) {
        int row = idx >> 3, u = idx & 7;
        uint32_t d = SWZ128(row * 128 + u * 16);
        *(uint4*)(smem + OFF_K + d)         = *(const uint4*)(Qhg + row * 64 + u * 8);
        *(uint4*)(smem + OFF_K + d + 16384) = *(const uint4*)(Qlg + row * 64 + u * 8);
    }
    __syncthreads();

    uint32_t qh[4][4], ql[4][4];
    {
        int r = wq * 16 + (lane & 15);
        #pragma unroll
        for (int ks = 0; ks < 4; ks++) {
            uint32_t a = sb + OFF_K + SWZ128(r * 128 + ks * 32 + (lane >> 4) * 16);
            ldsm4(qh[ks][0], qh[ks][1], qh[ks][2], qh[ks][3], a);
            ldsm4(ql[ks][0], ql[ks][1], ql[ks][2], ql[ks][3], a + 16384);
        }
    }
    __syncthreads();

    // ---- async tile loader: K hi+lo, V fp16 (512 threads) ----
    auto loadKV = [&](int it, int buf) {
        uint32_t kb = sb + OFF_K + (uint32_t)buf * 32768u;
        uint32_t vb = sb + OFF_V + (uint32_t)buf * 16384u;
        const __nv_bfloat16* kh = Khg + (size_t)it * 128 * 64;
        const __nv_bfloat16* kl = Klg + (size_t)it * 128 * 64;
        for (int idx = tid; idx < 1024; idx += 512) {
            int row = idx >> 3, u = idx & 7;
            uint32_t d = kb + SWZ128(row * 128 + u * 16);
            cpasync16(d,         kh + row * 64 + u * 8);
            cpasync16(d + 16384, kl + row * 64 + u * 8);
        }
        for (int idx = tid; idx < 1024; idx += 512) {
            int c = idx >> 4, u = idx & 15;
            cpasync16(vb + SWZ256(c * 256 + u * 16), Vfg + (size_t)c * 4096 + it * 128 + u * 8);
        }
        CP_COMMIT();
    };

    loadKV(0, 0);
    loadKV(1, 1);

    const float NEG_INF = __int_as_float(0xff800000u);
    float oacc[8][4];
    #pragma unroll
    for (int i = 0; i < 8; i++)
        #pragma unroll
        for (int j = 0; j < 4; j++) oacc[i][j] = 0.0f;
    float lsum[2] = {0.f, 0.f};
    float mrow[2] = {NEG_INF, NEG_INF};

    for (int it = 0; it < 32; it++) {
        if (it + 1 < 32) { CP_WAIT1(); } else { CP_WAIT0(); }
        __syncthreads();

        const uint32_t kb = sb + OFF_K + (uint32_t)(it & 1) * 32768u;
        const uint32_t vb = sb + OFF_V + (uint32_t)(it & 1) * 16384u;

        // ---- S (bf16 3-split) for chunk kc ----
        auto S_step = [&](int kc, float sv[2][4]) {
            #pragma unroll
            for (int j = 0; j < 2; j++) {
                const int nt = kc * 2 + j;
                uint32_t bh[8], bl[8];
                const int br = nt * 8 + (lane & 7);
                #pragma unroll
                for (int ks2 = 0; ks2 < 2; ks2++) {
                    uint32_t a = kb + SWZ128(br * 128 + ks2 * 64 + (lane >> 3) * 16);
                    ldsm4(bh[4*ks2+0], bh[4*ks2+1], bh[4*ks2+2], bh[4*ks2+3], a);
                    ldsm4(bl[4*ks2+0], bl[4*ks2+1], bl[4*ks2+2], bl[4*ks2+3], a + 16384);
                }
                float sa[4] = {0.f, 0.f, 0.f, 0.f};
                float sb2[4] = {0.f, 0.f, 0.f, 0.f};
                float sc[4] = {0.f, 0.f, 0.f, 0.f};
                #pragma unroll
                for (int ks = 0; ks < 4; ks++) {
                    mma16816(sa,  qh[ks][0], qh[ks][1], qh[ks][2], qh[ks][3], bh[2*ks], bh[2*ks+1]);
                    mma16816(sb2, qh[ks][0], qh[ks][1], qh[ks][2], qh[ks][3], bl[2*ks], bl[2*ks+1]);
                    mma16816(sc,  ql[ks][0], ql[ks][1], ql[ks][2], ql[ks][3], bh[2*ks], bh[2*ks+1]);
                }
                #pragma unroll
                for (int i = 0; i < 4; i++) sv[j][i] = (sa[i] + sb2[i]) + sc[i];
            }
        };

        // ---- PV (fp16 single) for chunk cp ----
        auto PV_step = [&](int cp, const uint32_t pa[4]) {
            #pragma unroll
            for (int cnp = 0; cnp < 4; cnp++) {
                const int row = cnp * 16 + (lane >> 4) * 8 + (lane & 7);
                const int chunk = cp * 2 + ((lane >> 3) & 1);
                uint32_t a = vb + SWZ256(row * 256 + chunk * 16);
                uint32_t vh[4];
                ldsm4(vh[0], vh[1], vh[2], vh[3], a);
                mma16816h(oacc[2*cnp],   pa[0], pa[1], pa[2], pa[3], vh[0], vh[1]);
                mma16816h(oacc[2*cnp+1], pa[0], pa[1], pa[2], pa[3], vh[2], vh[3]);
            }
        };

        // ---- online softmax: update running max, rescale O lazily, emit p ----
        auto softmax_step = [&](const float sv[2][4], uint32_t pa[4]) {
            float t0 = fmaxf(fmaxf(sv[0][0], sv[0][1]), fmaxf(sv[1][0], sv[1][1]));
            float t1 = fmaxf(fmaxf(sv[0][2], sv[0][3]), fmaxf(sv[1][2], sv[1][3]));
            t0 = fmaxf(t0, __shfl_xor_sync(0xffffffffu, t0, 1));
            t0 = fmaxf(t0, __shfl_xor_sync(0xffffffffu, t0, 2));
            t1 = fmaxf(t1, __shfl_xor_sync(0xffffffffu, t1, 1));
            t1 = fmaxf(t1, __shfl_xor_sync(0xffffffffu, t1, 2));

            float m0 = fmaxf(mrow[0], t0);
            float m1 = fmaxf(mrow[1], t1);
            float a0 = __expf(mrow[0] - m0);   // 1 if max unchanged
            float a1 = __expf(mrow[1] - m1);
            mrow[0] = m0;
            mrow[1] = m1;

            if (a0 < 1.0f || a1 < 1.0f) {      // lazy rescale (rare)
                lsum[0] *= a0;
                lsum[1] *= a1;
                #pragma unroll
                for (int cn = 0; cn < 8; cn++) {
                    oacc[cn][0] *= a0;
                    oacc[cn][1] *= a0;
                    oacc[cn][2] *= a1;
                    oacc[cn][3] *= a1;
                }
            }

            #pragma unroll
            for (int j = 0; j < 2; j++) {
                float p0 = __expf(sv[j][0] - m0);
                float p1 = __expf(sv[j][1] - m0);
                float p2 = __expf(sv[j][2] - m1);
                float p3 = __expf(sv[j][3] - m1);
                __half2 h01 = __floats2half2_rn(p0, p1);
                __half2 h23 = __floats2half2_rn(p2, p3);
                float2 f01 = __half22float2(h01);
                float2 f23 = __half22float2(h23);
                lsum[0] += f01.x + f01.y;
                lsum[1] += f23.x + f23.y;
                pa[2*j]   = *(uint32_t*)&h01;
                pa[2*j+1] = *(uint32_t*)&h23;
            }
        };

        // ---- this group's 4 chunks, pipelined ----
        const int kc0 = grp * 4;
        uint32_t pa[4];
        {
            float sv[2][4];
            S_step(kc0, sv);
            softmax_step(sv, pa);
        }
        #pragma unroll 1
        for (int kc = kc0 + 1; kc < kc0 + 4; kc++) {
            float sv[2][4];
            S_step(kc, sv);
            PV_step(kc - 1, pa);
            softmax_step(sv, pa);
        }
        PV_step(kc0 + 3, pa);

        __syncthreads();
        if (it + 2 < 32) loadKV(it + 2, it & 1);
    }

    // ---- epilogue: quad-reduce lsum, max-aware group merge, store ----
    #pragma unroll
    for (int h2 = 0; h2 < 2; h2++) {
        lsum[h2] += __shfl_xor_sync(0xffffffffu, lsum[h2], 1);
        lsum[h2] += __shfl_xor_sync(0xffffffffu, lsum[h2], 2);
    }

    float* pO = (float*)smem;                    // [64c][128q] 32KB
    float* pLl = (float*)(smem + OFF_M);         // [128] group-1 lsum
    float* pLm = (float*)(smem + OFF_M + 512);   // [128] group-1 max

    const int q0 = wq * 16 + (lane >> 2);

    if (grp == 1) {
        #pragma unroll
        for (int cn = 0; cn < 8; cn++) {
            const int c = cn * 8 + 2 * (lane & 3);
            pO[c * 128 + q0]           = oacc[cn][0];
            pO[(c + 1) * 128 + q0]     = oacc[cn][1];
            pO[c * 128 + q0 + 8]       = oacc[cn][2];
            pO[(c + 1) * 128 + q0 + 8] = oacc[cn][3];
        }
        if ((lane & 3) == 0) {
            pLl[q0]     = lsum[0];  pLl[q0 + 8] = lsum[1];
            pLm[q0]     = mrow[0];  pLm[q0 + 8] = mrow[1];
        }
    }
    __syncthreads();
    if (grp == 0) {
        #pragma unroll
        for (int h2 = 0; h2 < 2; h2++) {
            const int qq = q0 + 8 * h2;
            float m1v = pLm[qq], l1v = pLl[qq];
            float M = fmaxf(mrow[h2], m1v);
            float f0 = __expf(mrow[h2] - M);
            float f1 = __expf(m1v - M);
            float inv = 1.0f / (lsum[h2] * f0 + l1v * f1);
            float g0 = f0 * inv, g1 = f1 * inv;
            #pragma unroll
            for (int cn = 0; cn < 8; cn++) {
                const int c = cn * 8 + 2 * (lane & 3);
                pO[c * 128 + qq]       = oacc[cn][2*h2]   * g0 + pO[c * 128 + qq]       * g1;
                pO[(c + 1) * 128 + qq] = oacc[cn][2*h2+1] * g0 + pO[(c + 1) * 128 + qq] * g1;
            }
        }
    }
    __syncthreads();

    float* outb = out + (size_t)b * 64 * 4096;
    for (int idx = tid; idx < 8192; idx += 512) {
        int c = idx >> 7, qq = idx & 127;
        outb[(size_t)c * 4096 + n0 + qq] = pO[idx];
    }
}

extern "C" void kernel_launch(void* const* d_in, const int* in_sizes, int n_in,
                              void* d_out, int out_size)
{
    const float* x  = (const float*)d_in[0];
    const float* Wq = (const float*)d_in[1];
    const float* bq = (const float*)d_in[2];
    const float* Wk = (const float*)d_in[3];
    const float* bk = (const float*)d_in[4];
    const float* Wv = (const float*)d_in[5];
    const float* bv = (const float*)d_in[6];
    float* out = (float*)d_out;

    qkv_kernel<<<dim3(64, NB, 3), 256>>>(x, Wq, bq, Wk, bk, Wv, bv);

    cudaFuncSetAttribute(attn_kernel, cudaFuncAttributeMaxDynamicSharedMemorySize, ATTN_SMEM);
    attn_kernel<<<dim3(32, NB), 512, ATTN_SMEM>>>(out);
}

// round 17
// speedup vs baseline: 1.2532x; 1.0425x over previous
#include <cuda_runtime.h>
#include <cuda_bf16.h>
#include <cuda_fp16.h>
#include <stdint.h>

#define NB 4
#define NC 64
#define NN 4096

// bf16 hi/lo split Q/K (Q pre-scaled by log2(e)) + fp16 single V.
__device__ __nv_bfloat16 g_Qh[NB*NN*NC];   // (B, N, C)
__device__ __nv_bfloat16 g_Ql[NB*NN*NC];
__device__ __nv_bfloat16 g_Kh[NB*NN*NC];   // (B, N, C)
__device__ __nv_bfloat16 g_Kl[NB*NN*NC];
__device__ __half        g_Vf[NB*NC*NN];   // (B, C, N)

// ---------------------------------------------------------------------------
// Arch-agnostic tensor-core helpers (sm_80+ PTX only: ldmatrix / mma / cp.async)
// ---------------------------------------------------------------------------
__device__ __forceinline__ uint32_t smem_u32(const void* p) {
    uint32_t a;
    asm("{ .reg .u64 t; cvta.to.shared.u64 t, %1; cvt.u32.u64 %0, t; }" : "=r"(a) : "l"(p));
    return a;
}

#define SWZ128(x) ((uint32_t)(x) ^ ((((uint32_t)(x)) >> 3) & 0x70u))
#define SWZ256(x) ((uint32_t)(x) ^ ((((uint32_t)(x)) >> 4) & 0x70u))

__device__ __forceinline__ void ldsm4(uint32_t &r0, uint32_t &r1, uint32_t &r2, uint32_t &r3,
                                      uint32_t a) {
    asm volatile("ldmatrix.sync.aligned.m8n8.x4.shared.b16 {%0,%1,%2,%3}, [%4];"
                 : "=r"(r0), "=r"(r1), "=r"(r2), "=r"(r3) : "r"(a));
}

__device__ __forceinline__ void mma16816(float c[4],
                                         uint32_t a0, uint32_t a1, uint32_t a2, uint32_t a3,
                                         uint32_t b0, uint32_t b1) {
    asm volatile("mma.sync.aligned.m16n8k16.row.col.f32.bf16.bf16.f32 "
                 "{%0,%1,%2,%3}, {%4,%5,%6,%7}, {%8,%9}, {%0,%1,%2,%3};"
                 : "+f"(c[0]), "+f"(c[1]), "+f"(c[2]), "+f"(c[3])
                 : "r"(a0), "r"(a1), "r"(a2), "r"(a3), "r"(b0), "r"(b1));
}

__device__ __forceinline__ void mma16816h(float c[4],
                                          uint32_t a0, uint32_t a1, uint32_t a2, uint32_t a3,
                                          uint32_t b0, uint32_t b1) {
    asm volatile("mma.sync.aligned.m16n8k16.row.col.f32.f16.f16.f32 "
                 "{%0,%1,%2,%3}, {%4,%5,%6,%7}, {%8,%9}, {%0,%1,%2,%3};"
                 : "+f"(c[0]), "+f"(c[1]), "+f"(c[2]), "+f"(c[3])
                 : "r"(a0), "r"(a1), "r"(a2), "r"(a3), "r"(b0), "r"(b1));
}

__device__ __forceinline__ void cpasync16(uint32_t s, const void* g) {
    asm volatile("cp.async.cg.shared.global [%0], [%1], 16;"
                 :: "r"(s), "l"(__cvta_generic_to_global(g)) : "memory");
}
#define CP_COMMIT() asm volatile("cp.async.commit_group;" ::: "memory")
#define CP_WAIT1()  asm volatile("cp.async.wait_group 1;" ::: "memory")
#define CP_WAIT0()  asm volatile("cp.async.wait_group 0;" ::: "memory")

// ---------------------------------------------------------------------------
// QKV projection: Q/K bf16 hi/lo (Q scaled by log2e), V fp16 single.
// ---------------------------------------------------------------------------
__global__ __launch_bounds__(256) void qkv_kernel(
    const float* __restrict__ x,
    const float* __restrict__ Wq, const float* __restrict__ bq,
    const float* __restrict__ Wk, const float* __restrict__ bk,
    const float* __restrict__ Wv, const float* __restrict__ bv)
{
    __shared__ float xs[64 * 64];
    __shared__ float wts[64 * 65];

    const int tid = threadIdx.x;
    const int b = blockIdx.y;
    const int n0 = blockIdx.x * 64;
    const int m  = blockIdx.z;

    const float* W = (m == 0) ? Wq : (m == 1) ? Wk : Wv;
    const float* bias_v = (m == 0) ? bq : (m == 1) ? bk : bv;

    for (int idx = tid; idx < 4096; idx += 256) {
        int c = idx >> 6, nn = idx & 63;
        xs[idx] = x[(size_t)(b * 64 + c) * 4096 + n0 + nn];
    }
    for (int idx = tid; idx < 4096; idx += 256)
        wts[(idx & 63) * 65 + (idx >> 6)] = W[idx];
    __syncthreads();

    const int co = tid & 63;
    const int g  = tid >> 6;

    float acc[16];
    const float bias = bias_v[co];
    #pragma unroll
    for (int i = 0; i < 16; i++) acc[i] = bias;

    #pragma unroll 4
    for (int c = 0; c < 64; c++) {
        float w = wts[c * 65 + co];
        const float4* xp = (const float4*)(xs + c * 64 + g * 16);
        #pragma unroll
        for (int r = 0; r < 4; r++) {
            float4 xv = xp[r];
            acc[4 * r + 0] += w * xv.x;
            acc[4 * r + 1] += w * xv.y;
            acc[4 * r + 2] += w * xv.z;
            acc[4 * r + 3] += w * xv.w;
        }
    }

    const int nbase = n0 + g * 16;
    if (m < 2) {
        if (m == 0) {   // fold log2(e) into Q -> S is in log2 domain
            #pragma unroll
            for (int i = 0; i < 16; i++) acc[i] *= 1.4426950408889634f;
        }
        __nv_bfloat16* Dh = (m == 0) ? g_Qh : g_Kh;
        __nv_bfloat16* Dl = (m == 0) ? g_Ql : g_Kl;
        #pragma unroll
        for (int i = 0; i < 16; i++) {
            float a = acc[i];
            __nv_bfloat16 h = __float2bfloat16(a);
            __nv_bfloat16 l = __float2bfloat16(a - __bfloat162float(h));
            size_t off = ((size_t)(b * 4096 + nbase + i)) * 64 + co;
            Dh[off] = h; Dl[off] = l;
        }
    } else {
        unsigned wh[8];
        #pragma unroll
        for (int i = 0; i < 8; i++) {
            __half2 h = __floats2half2_rn(acc[2 * i], acc[2 * i + 1]);
            wh[i] = *(unsigned*)&h;
        }
        size_t off = ((size_t)(b * 64 + co)) * 4096 + nbase;
        *(uint4*)(g_Vf + off)     = make_uint4(wh[0], wh[1], wh[2], wh[3]);
        *(uint4*)(g_Vf + off + 8) = make_uint4(wh[4], wh[5], wh[6], wh[7]);
    }
}

// ---------------------------------------------------------------------------
// Fused flash attention, single pass, online row max (log2 domain), fp16 PV.
// 512 thr = 16 warps = 8 q-warps x 2 k-groups; warp owns 16 q rows.
// Double-tile of 256 keys per period; group g owns its private 128-key
// subtile -> 8 pipelined chunks between barriers, 32 barriers total.
// smem: K [2 dbuf][2 sub][hi/lo][128x64 SW128] 128KB
//       + V [2 dbuf][2 sub][64x128 fp16 SW256] 64KB + merge 1KB = 193KB.
// ---------------------------------------------------------------------------
#define OFF_K 0u
#define OFF_V 131072u
#define OFF_M 196608u
#define ATTN_SMEM 197632u

__global__ void __launch_bounds__(512, 1) attn_kernel(float* __restrict__ out)
{
    extern __shared__ __align__(1024) char smem[];
    const uint32_t sb = smem_u32(smem);
    const int tid  = threadIdx.x;
    const int lane = tid & 31;
    const int w    = tid >> 5;
    const int wq   = w & 7;        // q warp: rows [16wq, 16wq+16)
    const int grp  = w >> 3;       // k-split group 0/1 (owns subtile grp)
    const int b    = blockIdx.y;
    const int n0   = blockIdx.x * 128;

    const __nv_bfloat16* Qhg = g_Qh + ((size_t)(b * 4096 + n0)) * 64;
    const __nv_bfloat16* Qlg = g_Ql + ((size_t)(b * 4096 + n0)) * 64;
    const __nv_bfloat16* Khg = g_Kh + ((size_t)b * 4096) * 64;
    const __nv_bfloat16* Klg = g_Kl + ((size_t)b * 4096) * 64;
    const __half*        Vfg = g_Vf + (size_t)b * 64 * 4096;

    // ---- stage Q (hi at OFF_K, lo at +16KB), extract A-fragments ----
    for (int idx = tid; idx < 1024; idx += 512) {
        int row = idx >> 3, u = idx & 7;
        uint32_t d = SWZ128(row * 128 + u * 16);
        *(uint4*)(smem + OFF_K + d)         = *(const uint4*)(Qhg + row * 64 + u * 8);
        *(uint4*)(smem + OFF_K + d + 16384) = *(const uint4*)(Qlg + row * 64 + u * 8);
    }
    __syncthreads();

    uint32_t qh[4][4], ql[4][4];
    {
        int r = wq * 16 + (lane & 15);
        #pragma unroll
        for (int ks = 0; ks < 4; ks++) {
            uint32_t a = sb + OFF_K + SWZ128(r * 128 + ks * 32 + (lane >> 4) * 16);
            ldsm4(qh[ks][0], qh[ks][1], qh[ks][2], qh[ks][3], a);
            ldsm4(ql[ks][0], ql[ks][1], ql[ks][2], ql[ks][3], a + 16384);
        }
    }
    __syncthreads();

    // ---- async double-tile loader: 256 keys (K hi/lo + V fp16) ----
    auto loadDT = [&](int dt, int buf) {
        uint32_t kb = sb + OFF_K + (uint32_t)buf * 65536u;
        uint32_t vb = sb + OFF_V + (uint32_t)buf * 32768u;
        const __nv_bfloat16* kh = Khg + (size_t)dt * 256 * 64;
        const __nv_bfloat16* kl = Klg + (size_t)dt * 256 * 64;
        // K: 2048 uint4 each of hi/lo; row r in 0..255
        for (int idx = tid; idx < 2048; idx += 512) {
            int r = idx >> 3, u = idx & 7;
            uint32_t d = kb + (uint32_t)(r >> 7) * 32768u + SWZ128((r & 127) * 128 + u * 16);
            cpasync16(d,         kh + r * 64 + u * 8);
            cpasync16(d + 16384, kl + r * 64 + u * 8);
        }
        // V: 2048 uint4; c in 0..63, 32 uint4 per row of 256 keys
        for (int idx = tid; idx < 2048; idx += 512) {
            int c = idx >> 5, u = idx & 31;
            int st = u >> 4, lu = u & 15;
            uint32_t d = vb + (uint32_t)st * 16384u + SWZ256(c * 256 + lu * 16);
            cpasync16(d, Vfg + (size_t)c * 4096 + dt * 256 + st * 128 + lu * 8);
        }
        CP_COMMIT();
    };

    loadDT(0, 0);
    loadDT(1, 1);

    const float NEG_INF = __int_as_float(0xff800000u);
    float oacc[8][4];
    #pragma unroll
    for (int i = 0; i < 8; i++)
        #pragma unroll
        for (int j = 0; j < 4; j++) oacc[i][j] = 0.0f;
    float lsum[2] = {0.f, 0.f};
    float mrow[2] = {NEG_INF, NEG_INF};

    for (int dt = 0; dt < 16; dt++) {
        if (dt + 1 < 16) { CP_WAIT1(); } else { CP_WAIT0(); }
        __syncthreads();

        // group-private subtile bases
        const uint32_t kb = sb + OFF_K + (uint32_t)(dt & 1) * 65536u + (uint32_t)grp * 32768u;
        const uint32_t vb = sb + OFF_V + (uint32_t)(dt & 1) * 32768u + (uint32_t)grp * 16384u;

        // ---- S (bf16 3-split) for local chunk kc (0..7) ----
        auto S_step = [&](int kc, float sv[2][4]) {
            #pragma unroll
            for (int j = 0; j < 2; j++) {
                const int nt = kc * 2 + j;
                uint32_t bh[8], bl[8];
                const int br = nt * 8 + (lane & 7);
                #pragma unroll
                for (int ks2 = 0; ks2 < 2; ks2++) {
                    uint32_t a = kb + SWZ128(br * 128 + ks2 * 64 + (lane >> 3) * 16);
                    ldsm4(bh[4*ks2+0], bh[4*ks2+1], bh[4*ks2+2], bh[4*ks2+3], a);
                    ldsm4(bl[4*ks2+0], bl[4*ks2+1], bl[4*ks2+2], bl[4*ks2+3], a + 16384);
                }
                float sa[4] = {0.f, 0.f, 0.f, 0.f};
                float sb2[4] = {0.f, 0.f, 0.f, 0.f};
                float sc[4] = {0.f, 0.f, 0.f, 0.f};
                #pragma unroll
                for (int ks = 0; ks < 4; ks++) {
                    mma16816(sa,  qh[ks][0], qh[ks][1], qh[ks][2], qh[ks][3], bh[2*ks], bh[2*ks+1]);
                    mma16816(sb2, qh[ks][0], qh[ks][1], qh[ks][2], qh[ks][3], bl[2*ks], bl[2*ks+1]);
                    mma16816(sc,  ql[ks][0], ql[ks][1], ql[ks][2], ql[ks][3], bh[2*ks], bh[2*ks+1]);
                }
                #pragma unroll
                for (int i = 0; i < 4; i++) sv[j][i] = (sa[i] + sb2[i]) + sc[i];
            }
        };

        // ---- PV (fp16 single) for local chunk cp ----
        auto PV_step = [&](int cp, const uint32_t pa[4]) {
            #pragma unroll
            for (int cnp = 0; cnp < 4; cnp++) {
                const int row = cnp * 16 + (lane >> 4) * 8 + (lane & 7);
                const int chunk = cp * 2 + ((lane >> 3) & 1);
                uint32_t a = vb + SWZ256(row * 256 + chunk * 16);
                uint32_t vh[4];
                ldsm4(vh[0], vh[1], vh[2], vh[3], a);
                mma16816h(oacc[2*cnp],   pa[0], pa[1], pa[2], pa[3], vh[0], vh[1]);
                mma16816h(oacc[2*cnp+1], pa[0], pa[1], pa[2], pa[3], vh[2], vh[3]);
            }
        };

        // ---- online softmax (log2 domain), predicated alpha rescale ----
        auto softmax_step = [&](const float sv[2][4], uint32_t pa[4]) {
            float t0 = fmaxf(fmaxf(sv[0][0], sv[0][1]), fmaxf(sv[1][0], sv[1][1]));
            float t1 = fmaxf(fmaxf(sv[0][2], sv[0][3]), fmaxf(sv[1][2], sv[1][3]));
            t0 = fmaxf(t0, __shfl_xor_sync(0xffffffffu, t0, 1));
            t0 = fmaxf(t0, __shfl_xor_sync(0xffffffffu, t0, 2));
            t1 = fmaxf(t1, __shfl_xor_sync(0xffffffffu, t1, 1));
            t1 = fmaxf(t1, __shfl_xor_sync(0xffffffffu, t1, 2));

            if (t0 > mrow[0] || t1 > mrow[1]) {    // max rose: rare after warmup
                float m0 = fmaxf(mrow[0], t0);
                float m1 = fmaxf(mrow[1], t1);
                float a0 = exp2f(mrow[0] - m0);
                float a1 = exp2f(mrow[1] - m1);
                mrow[0] = m0;
                mrow[1] = m1;
                lsum[0] *= a0;
                lsum[1] *= a1;
                #pragma unroll
                for (int cn = 0; cn < 8; cn++) {
                    oacc[cn][0] *= a0;
                    oacc[cn][1] *= a0;
                    oacc[cn][2] *= a1;
                    oacc[cn][3] *= a1;
                }
            }

            #pragma unroll
            for (int j = 0; j < 2; j++) {
                float p0 = exp2f(sv[j][0] - mrow[0]);
                float p1 = exp2f(sv[j][1] - mrow[0]);
                float p2 = exp2f(sv[j][2] - mrow[1]);
                float p3 = exp2f(sv[j][3] - mrow[1]);
                __half2 h01 = __floats2half2_rn(p0, p1);
                __half2 h23 = __floats2half2_rn(p2, p3);
                float2 f01 = __half22float2(h01);
                float2 f23 = __half22float2(h23);
                lsum[0] += f01.x + f01.y;
                lsum[1] += f23.x + f23.y;
                pa[2*j]   = *(uint32_t*)&h01;
                pa[2*j+1] = *(uint32_t*)&h23;
            }
        };

        // ---- 8 pipelined chunks in the group's private subtile ----
        uint32_t pa[4];
        {
            float sv[2][4];
            S_step(0, sv);
            softmax_step(sv, pa);
        }
        #pragma unroll 1
        for (int kc = 1; kc < 8; kc++) {
            float sv[2][4];
            S_step(kc, sv);
            PV_step(kc - 1, pa);
            softmax_step(sv, pa);
        }
        PV_step(7, pa);

        __syncthreads();
        if (dt + 2 < 16) loadDT(dt + 2, dt & 1);
    }

    // ---- epilogue: quad-reduce lsum, max-aware group merge, store ----
    #pragma unroll
    for (int h2 = 0; h2 < 2; h2++) {
        lsum[h2] += __shfl_xor_sync(0xffffffffu, lsum[h2], 1);
        lsum[h2] += __shfl_xor_sync(0xffffffffu, lsum[h2], 2);
    }

    float* pO = (float*)smem;                    // [64c][128q] 32KB
    float* pLl = (float*)(smem + OFF_M);         // [128] group-1 lsum
    float* pLm = (float*)(smem + OFF_M + 512);   // [128] group-1 max

    const int q0 = wq * 16 + (lane >> 2);

    if (grp == 1) {
        #pragma unroll
        for (int cn = 0; cn < 8; cn++) {
            const int c = cn * 8 + 2 * (lane & 3);
            pO[c * 128 + q0]           = oacc[cn][0];
            pO[(c + 1) * 128 + q0]     = oacc[cn][1];
            pO[c * 128 + q0 + 8]       = oacc[cn][2];
            pO[(c + 1) * 128 + q0 + 8] = oacc[cn][3];
        }
        if ((lane & 3) == 0) {
            pLl[q0]     = lsum[0];  pLl[q0 + 8] = lsum[1];
            pLm[q0]     = mrow[0];  pLm[q0 + 8] = mrow[1];
        }
    }
    __syncthreads();
    if (grp == 0) {
        #pragma unroll
        for (int h2 = 0; h2 < 2; h2++) {
            const int qq = q0 + 8 * h2;
            float m1v = pLm[qq], l1v = pLl[qq];
            float M = fmaxf(mrow[h2], m1v);
            float f0 = exp2f(mrow[h2] - M);
            float f1 = exp2f(m1v - M);
            float inv = 1.0f / (lsum[h2] * f0 + l1v * f1);
            float g0 = f0 * inv, g1 = f1 * inv;
            #pragma unroll
            for (int cn = 0; cn < 8; cn++) {
                const int c = cn * 8 + 2 * (lane & 3);
                pO[c * 128 + qq]       = oacc[cn][2*h2]   * g0 + pO[c * 128 + qq]       * g1;
                pO[(c + 1) * 128 + qq] = oacc[cn][2*h2+1] * g0 + pO[(c + 1) * 128 + qq] * g1;
            }
        }
    }
    __syncthreads();

    float* outb = out + (size_t)b * 64 * 4096;
    for (int idx = tid; idx < 8192; idx += 512) {
        int c = idx >> 7, qq = idx & 127;
        outb[(size_t)c * 4096 + n0 + qq] = pO[idx];
    }
}

extern "C" void kernel_launch(void* const* d_in, const int* in_sizes, int n_in,
                              void* d_out, int out_size)
{
    const float* x  = (const float*)d_in[0];
    const float* Wq = (const float*)d_in[1];
    const float* bq = (const float*)d_in[2];
    const float* Wk = (const float*)d_in[3];
    const float* bk = (const float*)d_in[4];
    const float* Wv = (const float*)d_in[5];
    const float* bv = (const float*)d_in[6];
    float* out = (float*)d_out;

    qkv_kernel<<<dim3(64, NB, 3), 256>>>(x, Wq, bq, Wk, bk, Wv, bv);

    cudaFuncSetAttribute(attn_kernel, cudaFuncAttributeMaxDynamicSharedMemorySize, ATTN_SMEM);
    attn_kernel<<<dim3(32, NB), 512, ATTN_SMEM>>>(out);
}